// round 13
// baseline (speedup 1.0000x reference)
#include <cuda_runtime.h>
#include <cuda_fp16.h>
#include <stdint.h>
#include <math.h>

#define NN    50000
#define EMAX  800000
#define INCH  128
#define FDIM  128
#define HEADS 4
#define HID   32
#define OUTC  10
#define GG    64
#define NEG_SLOPE 0.2f
#define CAP   96
#define AGG_BLOCKS 888   // persistent: 148 SMs x 6 resident CTAs

// ---------------- device scratch (zero-initialized at module load) ------
__device__ __align__(16) __half g_Ah[(size_t)NN * FDIM];
__device__ __align__(16) __half g_Hh[(size_t)NN * FDIM];
__device__ __align__(16) __half g_Wh1[FDIM * FDIM];
__device__ __align__(16) __half g_Wh2[FDIM * FDIM];
__device__ __align__(16) float g_ALS[(size_t)NN * HEADS];
__device__ __align__(16) float g_ALD[(size_t)NN * HEADS];
__device__ int   g_cursor[NN];          // ==0 at start of every call (restored by pool)
__device__ int   g_csrc[(size_t)NN * CAP];
__device__ float g_POOL[GG * FDIM];
__device__ float g_CNT[GG];

// ---------------- helpers ----------------
__device__ __forceinline__ float lrelu(float x) {
    return x > 0.f ? x : NEG_SLOPE * x;
}
__device__ __forceinline__ void ldm_x4(unsigned& r0, unsigned& r1, unsigned& r2,
                                       unsigned& r3, unsigned addr) {
    asm volatile("ldmatrix.sync.aligned.m8n8.x4.shared.b16 {%0,%1,%2,%3}, [%4];"
                 : "=r"(r0), "=r"(r1), "=r"(r2), "=r"(r3) : "r"(addr));
}
__device__ __forceinline__ void mma16816(float* d, const unsigned* a,
                                         unsigned b0, unsigned b1) {
    asm volatile(
        "mma.sync.aligned.m16n8k16.row.col.f32.f16.f16.f32 "
        "{%0,%1,%2,%3},{%4,%5,%6,%7},{%8,%9},{%0,%1,%2,%3};"
        : "+f"(d[0]), "+f"(d[1]), "+f"(d[2]), "+f"(d[3])
        : "r"(a[0]), "r"(a[1]), "r"(a[2]), "r"(a[3]), "r"(b0), "r"(b1));
}
__device__ __forceinline__ void pair_bar(int id) {
    asm volatile("bar.sync %0, 64;" :: "r"(id) : "memory");
}

// ---------------- launch 1: converts + POOL/CNT zero ---------------------
__global__ void init_all(const float* __restrict__ x, const float* __restrict__ W1,
                         const float* __restrict__ W2, int total4) {
    int i = blockIdx.x * blockDim.x + threadIdx.x;
    if (i < total4) {
        float4 v = __ldg((const float4*)x + i);
        uint2 w;
        *(half2*)&w.x = __floats2half2_rn(v.x, v.y);
        *(half2*)&w.y = __floats2half2_rn(v.z, v.w);
        ((uint2*)g_Ah)[i] = w;
    }
    if (i < FDIM * FDIM) {
        int k = i >> 7;
        int nn = i & 127;
        g_Wh1[nn * 128 + k] = __float2half(__ldg(&W1[i]));
        g_Wh2[nn * 128 + k] = __float2half(__ldg(&W2[i]));
    }
    if (i < GG * FDIM) g_POOL[i] = 0.f;
    if (i < GG) g_CNT[i] = 0.f;
}

// ---------------- launch 2: bucket-scatter edges -------------------------
__global__ void scatter_edges(const int* __restrict__ srcA,
                              const int* __restrict__ dstA, int E) {
    int i = blockIdx.x * blockDim.x + threadIdx.x;
    if (i >= E) return;
    int d = __ldg(&dstA[i]);
    int pos = atomicAdd(&g_cursor[d], 1);
    if (pos < CAP) g_csrc[(size_t)d * CAP + pos] = __ldg(&srcA[i]);
}

// ---------------- launch 3/5: fp16 mma GEMM + attention dots -------------
__global__ void __launch_bounds__(256) gemm_mma(const float* __restrict__ a_src,
                                                const float* __restrict__ a_dst,
                                                int n, int which) {
    __shared__ __half As[128 * 64];
    __shared__ __half Bs[128 * 64];
    const __half* Wh = which ? g_Wh2 : g_Wh1;
    const int tid = threadIdx.x;
    const int l = tid & 31;
    const int wid = tid >> 5;
    const int warp_m = wid >> 1;
    const int warp_n = wid & 1;
    const int row0 = blockIdx.x * 128;

    float acc[2][8][4];
#pragma unroll
    for (int i = 0; i < 2; i++)
#pragma unroll
        for (int j = 0; j < 8; j++)
#pragma unroll
            for (int c = 0; c < 4; c++) acc[i][j][c] = 0.f;

    const int grp = l >> 3;
    const int m8 = l & 7;
    int rowA[2];
#pragma unroll
    for (int i = 0; i < 2; i++) rowA[i] = warp_m * 32 + i * 16 + m8 + (grp & 1) * 8;
    const int kgA = grp >> 1;
    int nB[4];
#pragma unroll
    for (int jt = 0; jt < 4; jt++) nB[jt] = warp_n * 64 + jt * 16 + m8 + (grp >> 1) * 8;
    const int kgB = grp & 1;

    const unsigned as_base = (unsigned)__cvta_generic_to_shared(As);
    const unsigned bs_base = (unsigned)__cvta_generic_to_shared(Bs);

    for (int kc = 0; kc < 2; kc++) {
        if (kc) __syncthreads();
#pragma unroll
        for (int t = 0; t < 4; t++) {
            int e = tid + t * 256;
            int r = e >> 3;
            int g = e & 7;
            uint4 v = make_uint4(0, 0, 0, 0);
            if (row0 + r < n) v = ((const uint4*)g_Ah)[(size_t)(row0 + r) * 16 + kc * 8 + g];
            *((uint4*)(As + (r * 8 + (g ^ (r & 7))) * 8)) = v;
        }
#pragma unroll
        for (int t = 0; t < 4; t++) {
            int e = tid + t * 256;
            int r = e >> 3;
            int g = e & 7;
            uint4 v = ((const uint4*)Wh)[r * 16 + kc * 8 + g];
            *((uint4*)(Bs + (r * 8 + (g ^ (r & 7))) * 8)) = v;
        }
        __syncthreads();
#pragma unroll
        for (int ks = 0; ks < 4; ks++) {
            unsigned a[2][4];
            unsigned b[4][4];
#pragma unroll
            for (int i = 0; i < 2; i++) {
                int gr = ks * 2 + kgA;
                unsigned off = (unsigned)(rowA[i] * 8 + (gr ^ (rowA[i] & 7))) * 16u;
                ldm_x4(a[i][0], a[i][1], a[i][2], a[i][3], as_base + off);
            }
#pragma unroll
            for (int jt = 0; jt < 4; jt++) {
                int gr = ks * 2 + kgB;
                unsigned off = (unsigned)(nB[jt] * 8 + (gr ^ (nB[jt] & 7))) * 16u;
                ldm_x4(b[jt][0], b[jt][1], b[jt][2], b[jt][3], bs_base + off);
            }
#pragma unroll
            for (int i = 0; i < 2; i++)
#pragma unroll
                for (int j = 0; j < 8; j++) {
                    int jt = j >> 1;
                    int sel = (j & 1) * 2;
                    mma16816(acc[i][j], a[i], b[jt][sel], b[jt][sel + 1]);
                }
        }
    }

    const int quad = l >> 2;
    const int qt = l & 3;
    float wsrc[8][2];
    float wdst[8][2];
#pragma unroll
    for (int j = 0; j < 8; j++) {
        int c = warp_n * 64 + j * 8 + 2 * qt;
        wsrc[j][0] = __ldg(&a_src[c]);
        wsrc[j][1] = __ldg(&a_src[c + 1]);
        wdst[j][0] = __ldg(&a_dst[c]);
        wdst[j][1] = __ldg(&a_dst[c + 1]);
    }
    half2* H2 = (half2*)g_Hh;
#pragma unroll
    for (int i = 0; i < 2; i++) {
        int r_lo = row0 + warp_m * 32 + i * 16 + quad;
        int r_hi = r_lo + 8;
        float ps_lo[2] = {0.f, 0.f};
        float pd_lo[2] = {0.f, 0.f};
        float ps_hi[2] = {0.f, 0.f};
        float pd_hi[2] = {0.f, 0.f};
#pragma unroll
        for (int j = 0; j < 8; j++) {
            int hl = j >> 2;
            ps_lo[hl] += acc[i][j][0] * wsrc[j][0] + acc[i][j][1] * wsrc[j][1];
            pd_lo[hl] += acc[i][j][0] * wdst[j][0] + acc[i][j][1] * wdst[j][1];
            ps_hi[hl] += acc[i][j][2] * wsrc[j][0] + acc[i][j][3] * wsrc[j][1];
            pd_hi[hl] += acc[i][j][2] * wdst[j][0] + acc[i][j][3] * wdst[j][1];
        }
#pragma unroll
        for (int hl = 0; hl < 2; hl++) {
            ps_lo[hl] += __shfl_xor_sync(0xffffffffu, ps_lo[hl], 1);
            ps_lo[hl] += __shfl_xor_sync(0xffffffffu, ps_lo[hl], 2);
            pd_lo[hl] += __shfl_xor_sync(0xffffffffu, pd_lo[hl], 1);
            pd_lo[hl] += __shfl_xor_sync(0xffffffffu, pd_lo[hl], 2);
            ps_hi[hl] += __shfl_xor_sync(0xffffffffu, ps_hi[hl], 1);
            ps_hi[hl] += __shfl_xor_sync(0xffffffffu, ps_hi[hl], 2);
            pd_hi[hl] += __shfl_xor_sync(0xffffffffu, pd_hi[hl], 1);
            pd_hi[hl] += __shfl_xor_sync(0xffffffffu, pd_hi[hl], 2);
        }
        if (r_lo < n) {
#pragma unroll
            for (int j = 0; j < 8; j++) {
                int c = warp_n * 64 + j * 8 + 2 * qt;
                H2[(size_t)r_lo * 64 + (c >> 1)] =
                    __floats2half2_rn(acc[i][j][0], acc[i][j][1]);
            }
            if (qt == 0) {
#pragma unroll
                for (int hl = 0; hl < 2; hl++) {
                    g_ALS[r_lo * HEADS + warp_n * 2 + hl] = ps_lo[hl];
                    g_ALD[r_lo * HEADS + warp_n * 2 + hl] = pd_lo[hl];
                }
            }
        }
        if (r_hi < n) {
#pragma unroll
            for (int j = 0; j < 8; j++) {
                int c = warp_n * 64 + j * 8 + 2 * qt;
                H2[(size_t)r_hi * 64 + (c >> 1)] =
                    __floats2half2_rn(acc[i][j][2], acc[i][j][3]);
            }
            if (qt == 0) {
#pragma unroll
                for (int hl = 0; hl < 2; hl++) {
                    g_ALS[r_hi * HEADS + warp_n * 2 + hl] = ps_hi[hl];
                    g_ALD[r_hi * HEADS + warp_n * 2 + hl] = pd_hi[hl];
                }
            }
        }
    }
}

// ---------------- launch 4/6 (4 = PROFILED): persistent aggregation ------
// 2 warps per node, 4 nodes per CTA slot; persistent grid strides over
// node groups so CTA lifetimes equalize (no churn, no tail waves).
__global__ void __launch_bounds__(256) aggregate(const float* __restrict__ b,
                                                 int n, int do_elu) {
    __shared__ float s_acc[4][128];
    __shared__ float s_z[4][4];
    const int local = threadIdx.x >> 6;
    const int half = (threadIdx.x >> 5) & 1;
    const int lane = threadIdx.x & 31;
    const int h = lane >> 3;
    const unsigned FULL = 0xffffffffu;
    const uint2* H2 = (const uint2*)g_Hh;
    const int ngroups = (n + 3) >> 2;

    for (int grp = blockIdx.x; grp < ngroups; grp += gridDim.x) {
        const int d = grp * 4 + local;
        const bool active = d < n;

        float4 acc = make_float4(0.f, 0.f, 0.f, 0.f);
        float z = 0.f;

        if (active) {
            const float ald_h = __ldg(&g_ALD[d * 4 + h]);
            const int base = d * CAP;
            int cnt_all = min(__ldg(&g_cursor[d]), CAP);
            int mid = cnt_all >> 1;
            int lo = half ? mid : 0;
            int hi = half ? cnt_all : mid;

            if (half == 0) {
                float p = __expf(lrelu(__ldg(&g_ALS[d * 4 + h]) + ald_h));
                uint2 u = __ldg(H2 + (size_t)d * 32 + lane);
                float2 f01 = __half22float2(*(const half2*)&u.x);
                float2 f23 = __half22float2(*(const half2*)&u.y);
                acc = make_float4(p * f01.x, p * f01.y, p * f23.x, p * f23.y);
                z = p;
            }

            for (int j0 = lo; j0 < hi; j0 += 32) {
                int cnt = min(32, hi - j0);
                int my = (lane < cnt) ? __ldg(&g_csrc[base + j0 + lane]) : 0;
                int j = 0;
                for (; j + 8 <= cnt; j += 8) {
                    int ss[8];
#pragma unroll
                    for (int q = 0; q < 8; q++) ss[q] = __shfl_sync(FULL, my, j + q);
                    float av[8];
                    uint2 uv[8];
#pragma unroll
                    for (int q = 0; q < 8; q++) {
                        av[q] = __ldg(&g_ALS[ss[q] * 4 + h]);
                        uv[q] = __ldg(H2 + (size_t)ss[q] * 32 + lane);
                    }
#pragma unroll
                    for (int q = 0; q < 8; q++) {
                        float p = __expf(lrelu(av[q] + ald_h));
                        float2 fa = __half22float2(*(const half2*)&uv[q].x);
                        float2 fb = __half22float2(*(const half2*)&uv[q].y);
                        acc.x += p * fa.x;
                        acc.y += p * fa.y;
                        acc.z += p * fb.x;
                        acc.w += p * fb.y;
                        z += p;
                    }
                }
                for (; j + 4 <= cnt; j += 4) {
                    int ss[4];
#pragma unroll
                    for (int q = 0; q < 4; q++) ss[q] = __shfl_sync(FULL, my, j + q);
                    float av[4];
                    uint2 uv[4];
#pragma unroll
                    for (int q = 0; q < 4; q++) {
                        av[q] = __ldg(&g_ALS[ss[q] * 4 + h]);
                        uv[q] = __ldg(H2 + (size_t)ss[q] * 32 + lane);
                    }
#pragma unroll
                    for (int q = 0; q < 4; q++) {
                        float p = __expf(lrelu(av[q] + ald_h));
                        float2 fa = __half22float2(*(const half2*)&uv[q].x);
                        float2 fb = __half22float2(*(const half2*)&uv[q].y);
                        acc.x += p * fa.x;
                        acc.y += p * fa.y;
                        acc.z += p * fb.x;
                        acc.w += p * fb.y;
                        z += p;
                    }
                }
                for (; j < cnt; j++) {
                    int s = __shfl_sync(FULL, my, j);
                    float p = __expf(lrelu(__ldg(&g_ALS[s * 4 + h]) + ald_h));
                    uint2 us = __ldg(H2 + (size_t)s * 32 + lane);
                    float2 fa = __half22float2(*(const half2*)&us.x);
                    float2 fb = __half22float2(*(const half2*)&us.y);
                    acc.x += p * fa.x;
                    acc.y += p * fa.y;
                    acc.z += p * fb.x;
                    acc.w += p * fb.y;
                    z += p;
                }
            }
        }

        if (half == 1) {
            ((float4*)s_acc[local])[lane] = acc;
            if ((lane & 7) == 0) s_z[local][h] = z;
        }
        pair_bar(local + 1);
        if (half == 0 && active) {
            float4 pa = ((float4*)s_acc[local])[lane];
            acc.x += pa.x;
            acc.y += pa.y;
            acc.z += pa.z;
            acc.w += pa.w;
            z += s_z[local][h];

            float inv = 1.f / z;
            float4 bb = __ldg((const float4*)b + lane);
            float4 o;
            o.x = acc.x * inv + bb.x;
            o.y = acc.y * inv + bb.y;
            o.z = acc.z * inv + bb.z;
            o.w = acc.w * inv + bb.w;
            if (do_elu) {
                o.x = o.x > 0.f ? o.x : expm1f(o.x);
                o.y = o.y > 0.f ? o.y : expm1f(o.y);
                o.z = o.z > 0.f ? o.z : expm1f(o.z);
                o.w = o.w > 0.f ? o.w : expm1f(o.w);
            }
            uint2 wout;
            *(half2*)&wout.x = __floats2half2_rn(o.x, o.y);
            *(half2*)&wout.y = __floats2half2_rn(o.z, o.w);
            ((uint2*)g_Ah)[(size_t)d * 32 + lane] = wout;
        }
        pair_bar(local + 1);   // protect smem slot reuse across iterations
    }
}

// ---------------- launch 7: pooling + cursor restore ---------------------
#define POOL_CHUNK 128
__global__ void __launch_bounds__(128) pool_kernel(const int* __restrict__ batch, int n) {
    int gid = blockIdx.x * POOL_CHUNK + threadIdx.x;
    if (gid < NN) g_cursor[gid] = 0;

    int t = threadIdx.x;
    int start = blockIdx.x * POOL_CHUNK;
    if (start >= n) return;
    int end = min(start + POOL_CHUNK, n);
    int curg = __ldg(&batch[start]);
    float acc = 0.f;
    float cnt = 0.f;
    for (int nn = start; nn < end; nn++) {
        int g = __ldg(&batch[nn]);
        if (g != curg) {
            atomicAdd(&g_POOL[curg * FDIM + t], acc);
            if (t == 0) atomicAdd(&g_CNT[curg], cnt);
            acc = 0.f;
            cnt = 0.f;
            curg = g;
        }
        acc += __half2float(g_Ah[(size_t)nn * FDIM + t]);
        cnt += 1.f;
    }
    atomicAdd(&g_POOL[curg * FDIM + t], acc);
    if (t == 0) atomicAdd(&g_CNT[curg], cnt);
}

// ---------------- launch 8: final linear + softmax -----------------------
__global__ void __launch_bounds__(128) head_kernel(const float* __restrict__ Wl,
                                                   const float* __restrict__ bl,
                                                   float* __restrict__ out) {
    int g = blockIdx.x;
    __shared__ float p[FDIM];
    __shared__ float lg[OUTC];
    float c = fmaxf(g_CNT[g], 1.f);
    p[threadIdx.x] = g_POOL[g * FDIM + threadIdx.x] / c;
    __syncthreads();
    if (threadIdx.x < OUTC) {
        float s = bl[threadIdx.x];
#pragma unroll 16
        for (int k = 0; k < FDIM; k++) s += p[k] * Wl[k * OUTC + threadIdx.x];
        lg[threadIdx.x] = s;
    }
    __syncthreads();
    if (threadIdx.x == 0) {
        float mx = -1e30f;
        for (int o = 0; o < OUTC; o++) mx = fmaxf(mx, lg[o]);
        float ssum = 0.f;
        float e[OUTC];
        for (int o = 0; o < OUTC; o++) {
            e[o] = __expf(lg[o] - mx);
            ssum += e[o];
        }
        for (int o = 0; o < OUTC; o++) out[g * OUTC + o] = e[o] / ssum;
    }
}

// ---------------- host orchestration ----------------
extern "C" void kernel_launch(void* const* d_in, const int* in_sizes, int n_in,
                              void* d_out, int out_size) {
    const float* x     = (const float*)d_in[0];
    const float* W1    = (const float*)d_in[1];
    const float* a1s   = (const float*)d_in[2];
    const float* a1d   = (const float*)d_in[3];
    const float* b1    = (const float*)d_in[4];
    const float* W2    = (const float*)d_in[5];
    const float* a2s   = (const float*)d_in[6];
    const float* a2d   = (const float*)d_in[7];
    const float* b2    = (const float*)d_in[8];
    const float* Wl    = (const float*)d_in[9];
    const float* bl    = (const float*)d_in[10];
    const int*   ei    = (const int*)d_in[11];
    const int*   batch = (const int*)d_in[12];

    int n = in_sizes[0] / INCH;
    int E = in_sizes[11] / 2;
    const int* srcA = ei;
    const int* dstA = ei + E;

    int total4 = n * FDIM / 4;
    int gemm_blocks = (n + 127) / 128;

    init_all<<<(total4 + 255) / 256, 256>>>(x, W1, W2, total4);
    scatter_edges<<<(E + 255) / 256, 256>>>(srcA, dstA, E);

    gemm_mma<<<gemm_blocks, 256>>>(a1s, a1d, n, 0);
    aggregate<<<AGG_BLOCKS, 256>>>(b1, n, 1);

    gemm_mma<<<gemm_blocks, 256>>>(a2s, a2d, n, 1);
    aggregate<<<AGG_BLOCKS, 256>>>(b2, n, 0);

    pool_kernel<<<(n + POOL_CHUNK - 1) / POOL_CHUNK, 128>>>(batch, n);
    head_kernel<<<GG, 128>>>(Wl, bl, (float*)d_out);
}

// round 14
// speedup vs baseline: 1.0089x; 1.0089x over previous
#include <cuda_runtime.h>
#include <cuda_fp16.h>
#include <stdint.h>
#include <math.h>

#define NN    50000
#define EMAX  800000
#define INCH  128
#define FDIM  128
#define HEADS 4
#define HID   32
#define OUTC  10
#define GG    64
#define NEG_SLOPE 0.2f
#define CAP   96

// ---------------- device scratch (zero-initialized at module load) ------
__device__ __align__(16) __half g_Ah[(size_t)NN * FDIM];
__device__ __align__(16) __half g_Hh[(size_t)NN * FDIM];
__device__ __align__(16) __half g_Wh1[FDIM * FDIM];
__device__ __align__(16) __half g_Wh2[FDIM * FDIM];
__device__ __align__(16) float g_ALS[(size_t)NN * HEADS];
__device__ __align__(16) float g_ALD[(size_t)NN * HEADS];
__device__ int   g_cursor[NN];          // ==0 at start of every call (restored by pool)
__device__ int   g_csrc[(size_t)NN * CAP];
__device__ float g_POOL[GG * FDIM];
__device__ float g_CNT[GG];

// ---------------- helpers ----------------
__device__ __forceinline__ float lrelu(float x) {
    return x > 0.f ? x : NEG_SLOPE * x;
}
__device__ __forceinline__ void ldm_x4(unsigned& r0, unsigned& r1, unsigned& r2,
                                       unsigned& r3, unsigned addr) {
    asm volatile("ldmatrix.sync.aligned.m8n8.x4.shared.b16 {%0,%1,%2,%3}, [%4];"
                 : "=r"(r0), "=r"(r1), "=r"(r2), "=r"(r3) : "r"(addr));
}
__device__ __forceinline__ void mma16816(float* d, const unsigned* a,
                                         unsigned b0, unsigned b1) {
    asm volatile(
        "mma.sync.aligned.m16n8k16.row.col.f32.f16.f16.f32 "
        "{%0,%1,%2,%3},{%4,%5,%6,%7},{%8,%9},{%0,%1,%2,%3};"
        : "+f"(d[0]), "+f"(d[1]), "+f"(d[2]), "+f"(d[3])
        : "r"(a[0]), "r"(a[1]), "r"(a[2]), "r"(a[3]), "r"(b0), "r"(b1));
}

// ---------------- launch 1: converts + POOL/CNT zero ---------------------
__global__ void init_all(const float* __restrict__ x, const float* __restrict__ W1,
                         const float* __restrict__ W2, int total4) {
    int i = blockIdx.x * blockDim.x + threadIdx.x;
    if (i < total4) {
        float4 v = __ldg((const float4*)x + i);
        uint2 w;
        *(half2*)&w.x = __floats2half2_rn(v.x, v.y);
        *(half2*)&w.y = __floats2half2_rn(v.z, v.w);
        ((uint2*)g_Ah)[i] = w;
    }
    if (i < FDIM * FDIM) {
        int k = i >> 7;
        int nn = i & 127;
        g_Wh1[nn * 128 + k] = __float2half(__ldg(&W1[i]));
        g_Wh2[nn * 128 + k] = __float2half(__ldg(&W2[i]));
    }
    if (i < GG * FDIM) g_POOL[i] = 0.f;
    if (i < GG) g_CNT[i] = 0.f;
}

// ---------------- launch 2: bucket-scatter edges -------------------------
__global__ void scatter_edges(const int* __restrict__ srcA,
                              const int* __restrict__ dstA, int E) {
    int i = blockIdx.x * blockDim.x + threadIdx.x;
    if (i >= E) return;
    int d = __ldg(&dstA[i]);
    int pos = atomicAdd(&g_cursor[d], 1);
    if (pos < CAP) g_csrc[(size_t)d * CAP + pos] = __ldg(&srcA[i]);
}

// ---------------- launch 3/5: fp16 mma GEMM + attention dots -------------
__global__ void __launch_bounds__(256) gemm_mma(const float* __restrict__ a_src,
                                                const float* __restrict__ a_dst,
                                                int n, int which) {
    __shared__ __half As[128 * 64];
    __shared__ __half Bs[128 * 64];
    const __half* Wh = which ? g_Wh2 : g_Wh1;
    const int tid = threadIdx.x;
    const int l = tid & 31;
    const int wid = tid >> 5;
    const int warp_m = wid >> 1;
    const int warp_n = wid & 1;
    const int row0 = blockIdx.x * 128;

    float acc[2][8][4];
#pragma unroll
    for (int i = 0; i < 2; i++)
#pragma unroll
        for (int j = 0; j < 8; j++)
#pragma unroll
            for (int c = 0; c < 4; c++) acc[i][j][c] = 0.f;

    const int grp = l >> 3;
    const int m8 = l & 7;
    int rowA[2];
#pragma unroll
    for (int i = 0; i < 2; i++) rowA[i] = warp_m * 32 + i * 16 + m8 + (grp & 1) * 8;
    const int kgA = grp >> 1;
    int nB[4];
#pragma unroll
    for (int jt = 0; jt < 4; jt++) nB[jt] = warp_n * 64 + jt * 16 + m8 + (grp >> 1) * 8;
    const int kgB = grp & 1;

    const unsigned as_base = (unsigned)__cvta_generic_to_shared(As);
    const unsigned bs_base = (unsigned)__cvta_generic_to_shared(Bs);

    for (int kc = 0; kc < 2; kc++) {
        if (kc) __syncthreads();
#pragma unroll
        for (int t = 0; t < 4; t++) {
            int e = tid + t * 256;
            int r = e >> 3;
            int g = e & 7;
            uint4 v = make_uint4(0, 0, 0, 0);
            if (row0 + r < n) v = ((const uint4*)g_Ah)[(size_t)(row0 + r) * 16 + kc * 8 + g];
            *((uint4*)(As + (r * 8 + (g ^ (r & 7))) * 8)) = v;
        }
#pragma unroll
        for (int t = 0; t < 4; t++) {
            int e = tid + t * 256;
            int r = e >> 3;
            int g = e & 7;
            uint4 v = ((const uint4*)Wh)[r * 16 + kc * 8 + g];
            *((uint4*)(Bs + (r * 8 + (g ^ (r & 7))) * 8)) = v;
        }
        __syncthreads();
#pragma unroll
        for (int ks = 0; ks < 4; ks++) {
            unsigned a[2][4];
            unsigned b[4][4];
#pragma unroll
            for (int i = 0; i < 2; i++) {
                int gr = ks * 2 + kgA;
                unsigned off = (unsigned)(rowA[i] * 8 + (gr ^ (rowA[i] & 7))) * 16u;
                ldm_x4(a[i][0], a[i][1], a[i][2], a[i][3], as_base + off);
            }
#pragma unroll
            for (int jt = 0; jt < 4; jt++) {
                int gr = ks * 2 + kgB;
                unsigned off = (unsigned)(nB[jt] * 8 + (gr ^ (nB[jt] & 7))) * 16u;
                ldm_x4(b[jt][0], b[jt][1], b[jt][2], b[jt][3], bs_base + off);
            }
#pragma unroll
            for (int i = 0; i < 2; i++)
#pragma unroll
                for (int j = 0; j < 8; j++) {
                    int jt = j >> 1;
                    int sel = (j & 1) * 2;
                    mma16816(acc[i][j], a[i], b[jt][sel], b[jt][sel + 1]);
                }
        }
    }

    const int quad = l >> 2;
    const int qt = l & 3;
    float wsrc[8][2];
    float wdst[8][2];
#pragma unroll
    for (int j = 0; j < 8; j++) {
        int c = warp_n * 64 + j * 8 + 2 * qt;
        wsrc[j][0] = __ldg(&a_src[c]);
        wsrc[j][1] = __ldg(&a_src[c + 1]);
        wdst[j][0] = __ldg(&a_dst[c]);
        wdst[j][1] = __ldg(&a_dst[c + 1]);
    }
    half2* H2 = (half2*)g_Hh;
#pragma unroll
    for (int i = 0; i < 2; i++) {
        int r_lo = row0 + warp_m * 32 + i * 16 + quad;
        int r_hi = r_lo + 8;
        float ps_lo[2] = {0.f, 0.f};
        float pd_lo[2] = {0.f, 0.f};
        float ps_hi[2] = {0.f, 0.f};
        float pd_hi[2] = {0.f, 0.f};
#pragma unroll
        for (int j = 0; j < 8; j++) {
            int hl = j >> 2;
            ps_lo[hl] += acc[i][j][0] * wsrc[j][0] + acc[i][j][1] * wsrc[j][1];
            pd_lo[hl] += acc[i][j][0] * wdst[j][0] + acc[i][j][1] * wdst[j][1];
            ps_hi[hl] += acc[i][j][2] * wsrc[j][0] + acc[i][j][3] * wsrc[j][1];
            pd_hi[hl] += acc[i][j][2] * wdst[j][0] + acc[i][j][3] * wdst[j][1];
        }
#pragma unroll
        for (int hl = 0; hl < 2; hl++) {
            ps_lo[hl] += __shfl_xor_sync(0xffffffffu, ps_lo[hl], 1);
            ps_lo[hl] += __shfl_xor_sync(0xffffffffu, ps_lo[hl], 2);
            pd_lo[hl] += __shfl_xor_sync(0xffffffffu, pd_lo[hl], 1);
            pd_lo[hl] += __shfl_xor_sync(0xffffffffu, pd_lo[hl], 2);
            ps_hi[hl] += __shfl_xor_sync(0xffffffffu, ps_hi[hl], 1);
            ps_hi[hl] += __shfl_xor_sync(0xffffffffu, ps_hi[hl], 2);
            pd_hi[hl] += __shfl_xor_sync(0xffffffffu, pd_hi[hl], 1);
            pd_hi[hl] += __shfl_xor_sync(0xffffffffu, pd_hi[hl], 2);
        }
        if (r_lo < n) {
#pragma unroll
            for (int j = 0; j < 8; j++) {
                int c = warp_n * 64 + j * 8 + 2 * qt;
                H2[(size_t)r_lo * 64 + (c >> 1)] =
                    __floats2half2_rn(acc[i][j][0], acc[i][j][1]);
            }
            if (qt == 0) {
#pragma unroll
                for (int hl = 0; hl < 2; hl++) {
                    g_ALS[r_lo * HEADS + warp_n * 2 + hl] = ps_lo[hl];
                    g_ALD[r_lo * HEADS + warp_n * 2 + hl] = pd_lo[hl];
                }
            }
        }
        if (r_hi < n) {
#pragma unroll
            for (int j = 0; j < 8; j++) {
                int c = warp_n * 64 + j * 8 + 2 * qt;
                H2[(size_t)r_hi * 64 + (c >> 1)] =
                    __floats2half2_rn(acc[i][j][2], acc[i][j][3]);
            }
            if (qt == 0) {
#pragma unroll
                for (int hl = 0; hl < 2; hl++) {
                    g_ALS[r_hi * HEADS + warp_n * 2 + hl] = ps_hi[hl];
                    g_ALD[r_hi * HEADS + warp_n * 2 + hl] = pd_hi[hl];
                }
            }
        }
    }
}

// ---------------- launch 4/6 (4 = PROFILED): bucket-gather aggregation ---
// ONE warp per node. p computed in parallel across lanes: lane (q=lane>>2,
// hp=lane&3) handles edge q / head hp (8 edges x 4 heads = 32 lanes, one
// expf per lane), broadcast via STS -> per-edge LDS (same-warp ordered,
// pipelined, conflict-free). No inter-warp barrier or smem exchange.
__global__ void __launch_bounds__(256) aggregate(const float* __restrict__ b,
                                                 int n, int do_elu) {
    __shared__ float s_p[8][32];
    const int wid = threadIdx.x >> 5;
    const int lane = threadIdx.x & 31;
    const int d = (blockIdx.x * 256 + threadIdx.x) >> 5;
    if (d >= n) return;
    const int h = lane >> 3;
    const int hp = lane & 3;
    const unsigned FULL = 0xffffffffu;
    const uint2* H2 = (const uint2*)g_Hh;
    float* sp = s_p[wid];

    const float ald_h = __ldg(&g_ALD[d * 4 + h]);
    const float ald_p = __ldg(&g_ALD[d * 4 + hp]);
    const int base = d * CAP;
    const int cnt_all = min(__ldg(&g_cursor[d]), CAP);

    // self loop
    float p0 = __expf(lrelu(__ldg(&g_ALS[d * 4 + h]) + ald_h));
    uint2 u0 = __ldg(H2 + (size_t)d * 32 + lane);
    float2 f01 = __half22float2(*(const half2*)&u0.x);
    float2 f23 = __half22float2(*(const half2*)&u0.y);
    float4 acc = make_float4(p0 * f01.x, p0 * f01.y, p0 * f23.x, p0 * f23.y);
    float z = p0;

    for (int j0 = 0; j0 < cnt_all; j0 += 32) {
        int cnt = min(32, cnt_all - j0);
        int my = (lane < cnt) ? __ldg(&g_csrc[base + j0 + lane]) : 0;
        int j = 0;
        for (; j + 8 <= cnt; j += 8) {
            // parallel p: one expf per lane covering 8 edges x 4 heads
            int sq = __shfl_sync(FULL, my, j + (lane >> 2));
            float pq = __expf(lrelu(__ldg(&g_ALS[sq * 4 + hp]) + ald_p));
            sp[lane] = pq;
            int ss[8];
#pragma unroll
            for (int q = 0; q < 8; q++) ss[q] = __shfl_sync(FULL, my, j + q);
            uint2 uv[8];
#pragma unroll
            for (int q = 0; q < 8; q++) uv[q] = __ldg(H2 + (size_t)ss[q] * 32 + lane);
#pragma unroll
            for (int q = 0; q < 8; q++) {
                float p = sp[q * 4 + h];
                float2 fa = __half22float2(*(const half2*)&uv[q].x);
                float2 fb = __half22float2(*(const half2*)&uv[q].y);
                acc.x += p * fa.x;
                acc.y += p * fa.y;
                acc.z += p * fb.x;
                acc.w += p * fb.y;
                z += p;
            }
        }
        for (; j + 4 <= cnt; j += 4) {
            // lanes 0..15 produce valid p for edges 0..3 x heads 0..3
            int sq = __shfl_sync(FULL, my, j + ((lane >> 2) & 3));
            float pq = __expf(lrelu(__ldg(&g_ALS[sq * 4 + hp]) + ald_p));
            sp[lane] = pq;
            int ss[4];
#pragma unroll
            for (int q = 0; q < 4; q++) ss[q] = __shfl_sync(FULL, my, j + q);
            uint2 uv[4];
#pragma unroll
            for (int q = 0; q < 4; q++) uv[q] = __ldg(H2 + (size_t)ss[q] * 32 + lane);
#pragma unroll
            for (int q = 0; q < 4; q++) {
                float p = sp[q * 4 + h];
                float2 fa = __half22float2(*(const half2*)&uv[q].x);
                float2 fb = __half22float2(*(const half2*)&uv[q].y);
                acc.x += p * fa.x;
                acc.y += p * fa.y;
                acc.z += p * fb.x;
                acc.w += p * fb.y;
                z += p;
            }
        }
        for (; j < cnt; j++) {
            int s = __shfl_sync(FULL, my, j);
            float p = __expf(lrelu(__ldg(&g_ALS[s * 4 + h]) + ald_h));
            uint2 us = __ldg(H2 + (size_t)s * 32 + lane);
            float2 fa = __half22float2(*(const half2*)&us.x);
            float2 fb = __half22float2(*(const half2*)&us.y);
            acc.x += p * fa.x;
            acc.y += p * fa.y;
            acc.z += p * fb.x;
            acc.w += p * fb.y;
            z += p;
        }
    }

    float inv = 1.f / z;
    float4 bb = __ldg((const float4*)b + lane);
    float4 o;
    o.x = acc.x * inv + bb.x;
    o.y = acc.y * inv + bb.y;
    o.z = acc.z * inv + bb.z;
    o.w = acc.w * inv + bb.w;
    if (do_elu) {
        o.x = o.x > 0.f ? o.x : expm1f(o.x);
        o.y = o.y > 0.f ? o.y : expm1f(o.y);
        o.z = o.z > 0.f ? o.z : expm1f(o.z);
        o.w = o.w > 0.f ? o.w : expm1f(o.w);
    }
    uint2 wout;
    *(half2*)&wout.x = __floats2half2_rn(o.x, o.y);
    *(half2*)&wout.y = __floats2half2_rn(o.z, o.w);
    ((uint2*)g_Ah)[(size_t)d * 32 + lane] = wout;
}

// ---------------- launch 7: pooling + cursor restore ---------------------
#define POOL_CHUNK 128
__global__ void __launch_bounds__(128) pool_kernel(const int* __restrict__ batch, int n) {
    int gid = blockIdx.x * POOL_CHUNK + threadIdx.x;
    if (gid < NN) g_cursor[gid] = 0;

    int t = threadIdx.x;
    int start = blockIdx.x * POOL_CHUNK;
    if (start >= n) return;
    int end = min(start + POOL_CHUNK, n);
    int curg = __ldg(&batch[start]);
    float acc = 0.f;
    float cnt = 0.f;
    for (int nn = start; nn < end; nn++) {
        int g = __ldg(&batch[nn]);
        if (g != curg) {
            atomicAdd(&g_POOL[curg * FDIM + t], acc);
            if (t == 0) atomicAdd(&g_CNT[curg], cnt);
            acc = 0.f;
            cnt = 0.f;
            curg = g;
        }
        acc += __half2float(g_Ah[(size_t)nn * FDIM + t]);
        cnt += 1.f;
    }
    atomicAdd(&g_POOL[curg * FDIM + t], acc);
    if (t == 0) atomicAdd(&g_CNT[curg], cnt);
}

// ---------------- launch 8: final linear + softmax -----------------------
__global__ void __launch_bounds__(128) head_kernel(const float* __restrict__ Wl,
                                                   const float* __restrict__ bl,
                                                   float* __restrict__ out) {
    int g = blockIdx.x;
    __shared__ float p[FDIM];
    __shared__ float lg[OUTC];
    float c = fmaxf(g_CNT[g], 1.f);
    p[threadIdx.x] = g_POOL[g * FDIM + threadIdx.x] / c;
    __syncthreads();
    if (threadIdx.x < OUTC) {
        float s = bl[threadIdx.x];
#pragma unroll 16
        for (int k = 0; k < FDIM; k++) s += p[k] * Wl[k * OUTC + threadIdx.x];
        lg[threadIdx.x] = s;
    }
    __syncthreads();
    if (threadIdx.x == 0) {
        float mx = -1e30f;
        for (int o = 0; o < OUTC; o++) mx = fmaxf(mx, lg[o]);
        float ssum = 0.f;
        float e[OUTC];
        for (int o = 0; o < OUTC; o++) {
            e[o] = __expf(lg[o] - mx);
            ssum += e[o];
        }
        for (int o = 0; o < OUTC; o++) out[g * OUTC + o] = e[o] / ssum;
    }
}

// ---------------- host orchestration ----------------
extern "C" void kernel_launch(void* const* d_in, const int* in_sizes, int n_in,
                              void* d_out, int out_size) {
    const float* x     = (const float*)d_in[0];
    const float* W1    = (const float*)d_in[1];
    const float* a1s   = (const float*)d_in[2];
    const float* a1d   = (const float*)d_in[3];
    const float* b1    = (const float*)d_in[4];
    const float* W2    = (const float*)d_in[5];
    const float* a2s   = (const float*)d_in[6];
    const float* a2d   = (const float*)d_in[7];
    const float* b2    = (const float*)d_in[8];
    const float* Wl    = (const float*)d_in[9];
    const float* bl    = (const float*)d_in[10];
    const int*   ei    = (const int*)d_in[11];
    const int*   batch = (const int*)d_in[12];

    int n = in_sizes[0] / INCH;
    int E = in_sizes[11] / 2;
    const int* srcA = ei;
    const int* dstA = ei + E;

    int total4 = n * FDIM / 4;
    int gemm_blocks = (n + 127) / 128;
    int agg_blocks = (n * 32 + 255) / 256;

    init_all<<<(total4 + 255) / 256, 256>>>(x, W1, W2, total4);
    scatter_edges<<<(E + 255) / 256, 256>>>(srcA, dstA, E);

    gemm_mma<<<gemm_blocks, 256>>>(a1s, a1d, n, 0);
    aggregate<<<agg_blocks, 256>>>(b1, n, 1);

    gemm_mma<<<gemm_blocks, 256>>>(a2s, a2d, n, 1);
    aggregate<<<agg_blocks, 256>>>(b2, n, 0);

    pool_kernel<<<(n + POOL_CHUNK - 1) / POOL_CHUNK, 128>>>(batch, n);
    head_kernel<<<GG, 128>>>(Wl, bl, (float*)d_out);
}

// round 15
// speedup vs baseline: 1.4139x; 1.4015x over previous
#include <cuda_runtime.h>
#include <cuda_fp16.h>
#include <stdint.h>
#include <math.h>

#define NN    50000
#define EMAX  800000
#define INCH  128
#define FDIM  128
#define HEADS 4
#define HID   32
#define OUTC  10
#define GG    64
#define NEG_SLOPE 0.2f
#define CAP   96

// ---------------- device scratch (zero-initialized at module load) ------
__device__ __align__(16) __half g_Ah[(size_t)NN * FDIM];
__device__ __align__(16) __half g_Hh[(size_t)NN * FDIM];
__device__ __align__(16) __half g_Wh1[FDIM * FDIM];
__device__ __align__(16) __half g_Wh2[FDIM * FDIM];
__device__ __align__(16) float g_ALS[(size_t)NN * HEADS];
__device__ __align__(16) float g_ALD[(size_t)NN * HEADS];
__device__ int   g_cursor[NN];          // ==0 at start of every call (restored by pool)
__device__ int   g_csrc[(size_t)NN * CAP];
__device__ float g_POOL[GG * FDIM];
__device__ float g_CNT[GG];

// ---------------- helpers ----------------
__device__ __forceinline__ float lrelu(float x) {
    return x > 0.f ? x : NEG_SLOPE * x;
}
__device__ __forceinline__ void ldm_x4(unsigned& r0, unsigned& r1, unsigned& r2,
                                       unsigned& r3, unsigned addr) {
    asm volatile("ldmatrix.sync.aligned.m8n8.x4.shared.b16 {%0,%1,%2,%3}, [%4];"
                 : "=r"(r0), "=r"(r1), "=r"(r2), "=r"(r3) : "r"(addr));
}
__device__ __forceinline__ void mma16816(float* d, const unsigned* a,
                                         unsigned b0, unsigned b1) {
    asm volatile(
        "mma.sync.aligned.m16n8k16.row.col.f32.f16.f16.f32 "
        "{%0,%1,%2,%3},{%4,%5,%6,%7},{%8,%9},{%0,%1,%2,%3};"
        : "+f"(d[0]), "+f"(d[1]), "+f"(d[2]), "+f"(d[3])
        : "r"(a[0]), "r"(a[1]), "r"(a[2]), "r"(a[3]), "r"(b0), "r"(b1));
}

// ---------------- launch 1: converts + POOL/CNT zero ---------------------
__global__ void init_all(const float* __restrict__ x, const float* __restrict__ W1,
                         const float* __restrict__ W2, int total4) {
    int i = blockIdx.x * blockDim.x + threadIdx.x;
    if (i < total4) {
        float4 v = __ldg((const float4*)x + i);
        uint2 w;
        *(half2*)&w.x = __floats2half2_rn(v.x, v.y);
        *(half2*)&w.y = __floats2half2_rn(v.z, v.w);
        ((uint2*)g_Ah)[i] = w;
    }
    if (i < FDIM * FDIM) {
        int k = i >> 7;
        int nn = i & 127;
        g_Wh1[nn * 128 + k] = __float2half(__ldg(&W1[i]));
        g_Wh2[nn * 128 + k] = __float2half(__ldg(&W2[i]));
    }
    if (i < GG * FDIM) g_POOL[i] = 0.f;
    if (i < GG) g_CNT[i] = 0.f;
}

// ---------------- launch 2: bucket-scatter edges -------------------------
__global__ void scatter_edges(const int* __restrict__ srcA,
                              const int* __restrict__ dstA, int E) {
    int i = blockIdx.x * blockDim.x + threadIdx.x;
    if (i >= E) return;
    int d = __ldg(&dstA[i]);
    int pos = atomicAdd(&g_cursor[d], 1);
    if (pos < CAP) g_csrc[(size_t)d * CAP + pos] = __ldg(&srcA[i]);
}

// ---------------- launch 3/5: fp16 mma GEMM + attention dots -------------
__global__ void __launch_bounds__(256) gemm_mma(const float* __restrict__ a_src,
                                                const float* __restrict__ a_dst,
                                                int n, int which) {
    __shared__ __half As[128 * 64];
    __shared__ __half Bs[128 * 64];
    const __half* Wh = which ? g_Wh2 : g_Wh1;
    const int tid = threadIdx.x;
    const int l = tid & 31;
    const int wid = tid >> 5;
    const int warp_m = wid >> 1;
    const int warp_n = wid & 1;
    const int row0 = blockIdx.x * 128;

    float acc[2][8][4];
#pragma unroll
    for (int i = 0; i < 2; i++)
#pragma unroll
        for (int j = 0; j < 8; j++)
#pragma unroll
            for (int c = 0; c < 4; c++) acc[i][j][c] = 0.f;

    const int grp = l >> 3;
    const int m8 = l & 7;
    int rowA[2];
#pragma unroll
    for (int i = 0; i < 2; i++) rowA[i] = warp_m * 32 + i * 16 + m8 + (grp & 1) * 8;
    const int kgA = grp >> 1;
    int nB[4];
#pragma unroll
    for (int jt = 0; jt < 4; jt++) nB[jt] = warp_n * 64 + jt * 16 + m8 + (grp >> 1) * 8;
    const int kgB = grp & 1;

    const unsigned as_base = (unsigned)__cvta_generic_to_shared(As);
    const unsigned bs_base = (unsigned)__cvta_generic_to_shared(Bs);

    for (int kc = 0; kc < 2; kc++) {
        if (kc) __syncthreads();
#pragma unroll
        for (int t = 0; t < 4; t++) {
            int e = tid + t * 256;
            int r = e >> 3;
            int g = e & 7;
            uint4 v = make_uint4(0, 0, 0, 0);
            if (row0 + r < n) v = ((const uint4*)g_Ah)[(size_t)(row0 + r) * 16 + kc * 8 + g];
            *((uint4*)(As + (r * 8 + (g ^ (r & 7))) * 8)) = v;
        }
#pragma unroll
        for (int t = 0; t < 4; t++) {
            int e = tid + t * 256;
            int r = e >> 3;
            int g = e & 7;
            uint4 v = ((const uint4*)Wh)[r * 16 + kc * 8 + g];
            *((uint4*)(Bs + (r * 8 + (g ^ (r & 7))) * 8)) = v;
        }
        __syncthreads();
#pragma unroll
        for (int ks = 0; ks < 4; ks++) {
            unsigned a[2][4];
            unsigned b[4][4];
#pragma unroll
            for (int i = 0; i < 2; i++) {
                int gr = ks * 2 + kgA;
                unsigned off = (unsigned)(rowA[i] * 8 + (gr ^ (rowA[i] & 7))) * 16u;
                ldm_x4(a[i][0], a[i][1], a[i][2], a[i][3], as_base + off);
            }
#pragma unroll
            for (int jt = 0; jt < 4; jt++) {
                int gr = ks * 2 + kgB;
                unsigned off = (unsigned)(nB[jt] * 8 + (gr ^ (nB[jt] & 7))) * 16u;
                ldm_x4(b[jt][0], b[jt][1], b[jt][2], b[jt][3], bs_base + off);
            }
#pragma unroll
            for (int i = 0; i < 2; i++)
#pragma unroll
                for (int j = 0; j < 8; j++) {
                    int jt = j >> 1;
                    int sel = (j & 1) * 2;
                    mma16816(acc[i][j], a[i], b[jt][sel], b[jt][sel + 1]);
                }
        }
    }

    const int quad = l >> 2;
    const int qt = l & 3;
    float wsrc[8][2];
    float wdst[8][2];
#pragma unroll
    for (int j = 0; j < 8; j++) {
        int c = warp_n * 64 + j * 8 + 2 * qt;
        wsrc[j][0] = __ldg(&a_src[c]);
        wsrc[j][1] = __ldg(&a_src[c + 1]);
        wdst[j][0] = __ldg(&a_dst[c]);
        wdst[j][1] = __ldg(&a_dst[c + 1]);
    }
    half2* H2 = (half2*)g_Hh;
#pragma unroll
    for (int i = 0; i < 2; i++) {
        int r_lo = row0 + warp_m * 32 + i * 16 + quad;
        int r_hi = r_lo + 8;
        float ps_lo[2] = {0.f, 0.f};
        float pd_lo[2] = {0.f, 0.f};
        float ps_hi[2] = {0.f, 0.f};
        float pd_hi[2] = {0.f, 0.f};
#pragma unroll
        for (int j = 0; j < 8; j++) {
            int hl = j >> 2;
            ps_lo[hl] += acc[i][j][0] * wsrc[j][0] + acc[i][j][1] * wsrc[j][1];
            pd_lo[hl] += acc[i][j][0] * wdst[j][0] + acc[i][j][1] * wdst[j][1];
            ps_hi[hl] += acc[i][j][2] * wsrc[j][0] + acc[i][j][3] * wsrc[j][1];
            pd_hi[hl] += acc[i][j][2] * wdst[j][0] + acc[i][j][3] * wdst[j][1];
        }
#pragma unroll
        for (int hl = 0; hl < 2; hl++) {
            ps_lo[hl] += __shfl_xor_sync(0xffffffffu, ps_lo[hl], 1);
            ps_lo[hl] += __shfl_xor_sync(0xffffffffu, ps_lo[hl], 2);
            pd_lo[hl] += __shfl_xor_sync(0xffffffffu, pd_lo[hl], 1);
            pd_lo[hl] += __shfl_xor_sync(0xffffffffu, pd_lo[hl], 2);
            ps_hi[hl] += __shfl_xor_sync(0xffffffffu, ps_hi[hl], 1);
            ps_hi[hl] += __shfl_xor_sync(0xffffffffu, ps_hi[hl], 2);
            pd_hi[hl] += __shfl_xor_sync(0xffffffffu, pd_hi[hl], 1);
            pd_hi[hl] += __shfl_xor_sync(0xffffffffu, pd_hi[hl], 2);
        }
        if (r_lo < n) {
#pragma unroll
            for (int j = 0; j < 8; j++) {
                int c = warp_n * 64 + j * 8 + 2 * qt;
                H2[(size_t)r_lo * 64 + (c >> 1)] =
                    __floats2half2_rn(acc[i][j][0], acc[i][j][1]);
            }
            if (qt == 0) {
#pragma unroll
                for (int hl = 0; hl < 2; hl++) {
                    g_ALS[r_lo * HEADS + warp_n * 2 + hl] = ps_lo[hl];
                    g_ALD[r_lo * HEADS + warp_n * 2 + hl] = pd_lo[hl];
                }
            }
        }
        if (r_hi < n) {
#pragma unroll
            for (int j = 0; j < 8; j++) {
                int c = warp_n * 64 + j * 8 + 2 * qt;
                H2[(size_t)r_hi * 64 + (c >> 1)] =
                    __floats2half2_rn(acc[i][j][2], acc[i][j][3]);
            }
            if (qt == 0) {
#pragma unroll
                for (int hl = 0; hl < 2; hl++) {
                    g_ALS[r_hi * HEADS + warp_n * 2 + hl] = ps_hi[hl];
                    g_ALD[r_hi * HEADS + warp_n * 2 + hl] = pd_hi[hl];
                }
            }
        }
    }
}

// ---------------- launch 4/6 (4 = PROFILED): bucket-gather aggregation ---
// ONE warp per node; parallel p via STS/LDS broadcast; HFMA2 fp16
// accumulate flushed to fp32 per 32-edge chunk.
__global__ void __launch_bounds__(256) aggregate(const float* __restrict__ b,
                                                 int n, int do_elu) {
    __shared__ float s_p[8][32];
    const int wid = threadIdx.x >> 5;
    const int lane = threadIdx.x & 31;
    const int d = (blockIdx.x * 256 + threadIdx.x) >> 5;
    if (d >= n) return;
    const int h = lane >> 3;
    const int hp = lane & 3;
    const unsigned FULL = 0xffffffffu;
    const uint2* H2 = (const uint2*)g_Hh;
    float* sp = s_p[wid];

    const float ald_h = __ldg(&g_ALD[d * 4 + h]);
    const float ald_p = __ldg(&g_ALD[d * 4 + hp]);
    const int base = d * CAP;
    const int cnt_all = min(__ldg(&g_cursor[d]), CAP);

    // self loop (fp32)
    float p0 = __expf(lrelu(__ldg(&g_ALS[d * 4 + h]) + ald_h));
    uint2 u0 = __ldg(H2 + (size_t)d * 32 + lane);
    float2 f01 = __half22float2(*(const half2*)&u0.x);
    float2 f23 = __half22float2(*(const half2*)&u0.y);
    float4 acc = make_float4(p0 * f01.x, p0 * f01.y, p0 * f23.x, p0 * f23.y);
    float z = p0;

    const half2 hzero = __floats2half2_rn(0.f, 0.f);
    for (int j0 = 0; j0 < cnt_all; j0 += 32) {
        int cnt = min(32, cnt_all - j0);
        int my = (lane < cnt) ? __ldg(&g_csrc[base + j0 + lane]) : 0;
        half2 a01 = hzero;
        half2 a23 = hzero;
        int j = 0;
        for (; j + 8 <= cnt; j += 8) {
            int sq = __shfl_sync(FULL, my, j + (lane >> 2));
            float pq = __expf(lrelu(__ldg(&g_ALS[sq * 4 + hp]) + ald_p));
            sp[lane] = pq;
            int ss[8];
#pragma unroll
            for (int q = 0; q < 8; q++) ss[q] = __shfl_sync(FULL, my, j + q);
            uint2 uv[8];
#pragma unroll
            for (int q = 0; q < 8; q++) uv[q] = __ldg(H2 + (size_t)ss[q] * 32 + lane);
#pragma unroll
            for (int q = 0; q < 8; q++) {
                float p = sp[q * 4 + h];
                half2 ph = __float2half2_rn(p);
                a01 = __hfma2(ph, *(const half2*)&uv[q].x, a01);
                a23 = __hfma2(ph, *(const half2*)&uv[q].y, a23);
                z += p;
            }
        }
        for (; j + 4 <= cnt; j += 4) {
            int sq = __shfl_sync(FULL, my, j + ((lane >> 2) & 3));
            float pq = __expf(lrelu(__ldg(&g_ALS[sq * 4 + hp]) + ald_p));
            sp[lane] = pq;
            int ss[4];
#pragma unroll
            for (int q = 0; q < 4; q++) ss[q] = __shfl_sync(FULL, my, j + q);
            uint2 uv[4];
#pragma unroll
            for (int q = 0; q < 4; q++) uv[q] = __ldg(H2 + (size_t)ss[q] * 32 + lane);
#pragma unroll
            for (int q = 0; q < 4; q++) {
                float p = sp[q * 4 + h];
                half2 ph = __float2half2_rn(p);
                a01 = __hfma2(ph, *(const half2*)&uv[q].x, a01);
                a23 = __hfma2(ph, *(const half2*)&uv[q].y, a23);
                z += p;
            }
        }
        for (; j < cnt; j++) {
            int s = __shfl_sync(FULL, my, j);
            float p = __expf(lrelu(__ldg(&g_ALS[s * 4 + h]) + ald_h));
            uint2 us = __ldg(H2 + (size_t)s * 32 + lane);
            half2 ph = __float2half2_rn(p);
            a01 = __hfma2(ph, *(const half2*)&us.x, a01);
            a23 = __hfma2(ph, *(const half2*)&us.y, a23);
            z += p;
        }
        // flush fp16 partials
        float2 g01 = __half22float2(a01);
        float2 g23 = __half22float2(a23);
        acc.x += g01.x;
        acc.y += g01.y;
        acc.z += g23.x;
        acc.w += g23.y;
    }

    float inv = 1.f / z;
    float4 bb = __ldg((const float4*)b + lane);
    float4 o;
    o.x = acc.x * inv + bb.x;
    o.y = acc.y * inv + bb.y;
    o.z = acc.z * inv + bb.z;
    o.w = acc.w * inv + bb.w;
    if (do_elu) {
        o.x = o.x > 0.f ? o.x : expm1f(o.x);
        o.y = o.y > 0.f ? o.y : expm1f(o.y);
        o.z = o.z > 0.f ? o.z : expm1f(o.z);
        o.w = o.w > 0.f ? o.w : expm1f(o.w);
    }
    uint2 wout;
    *(half2*)&wout.x = __floats2half2_rn(o.x, o.y);
    *(half2*)&wout.y = __floats2half2_rn(o.z, o.w);
    ((uint2*)g_Ah)[(size_t)d * 32 + lane] = wout;
}

// ---------------- launch 7: pooling + cursor restore ---------------------
#define POOL_CHUNK 128
__global__ void __launch_bounds__(128) pool_kernel(const int* __restrict__ batch, int n) {
    int gid = blockIdx.x * POOL_CHUNK + threadIdx.x;
    if (gid < NN) g_cursor[gid] = 0;

    int t = threadIdx.x;
    int start = blockIdx.x * POOL_CHUNK;
    if (start >= n) return;
    int end = min(start + POOL_CHUNK, n);
    int curg = __ldg(&batch[start]);
    float acc = 0.f;
    float cnt = 0.f;
    for (int nn = start; nn < end; nn++) {
        int g = __ldg(&batch[nn]);
        if (g != curg) {
            atomicAdd(&g_POOL[curg * FDIM + t], acc);
            if (t == 0) atomicAdd(&g_CNT[curg], cnt);
            acc = 0.f;
            cnt = 0.f;
            curg = g;
        }
        acc += __half2float(g_Ah[(size_t)nn * FDIM + t]);
        cnt += 1.f;
    }
    atomicAdd(&g_POOL[curg * FDIM + t], acc);
    if (t == 0) atomicAdd(&g_CNT[curg], cnt);
}

// ---------------- launch 8: final linear + softmax -----------------------
__global__ void __launch_bounds__(128) head_kernel(const float* __restrict__ Wl,
                                                   const float* __restrict__ bl,
                                                   float* __restrict__ out) {
    int g = blockIdx.x;
    __shared__ float p[FDIM];
    __shared__ float lg[OUTC];
    float c = fmaxf(g_CNT[g], 1.f);
    p[threadIdx.x] = g_POOL[g * FDIM + threadIdx.x] / c;
    __syncthreads();
    if (threadIdx.x < OUTC) {
        float s = bl[threadIdx.x];
#pragma unroll 16
        for (int k = 0; k < FDIM; k++) s += p[k] * Wl[k * OUTC + threadIdx.x];
        lg[threadIdx.x] = s;
    }
    __syncthreads();
    if (threadIdx.x == 0) {
        float mx = -1e30f;
        for (int o = 0; o < OUTC; o++) mx = fmaxf(mx, lg[o]);
        float ssum = 0.f;
        float e[OUTC];
        for (int o = 0; o < OUTC; o++) {
            e[o] = __expf(lg[o] - mx);
            ssum += e[o];
        }
        for (int o = 0; o < OUTC; o++) out[g * OUTC + o] = e[o] / ssum;
    }
}

// ---------------- host orchestration ----------------
extern "C" void kernel_launch(void* const* d_in, const int* in_sizes, int n_in,
                              void* d_out, int out_size) {
    const float* x     = (const float*)d_in[0];
    const float* W1    = (const float*)d_in[1];
    const float* a1s   = (const float*)d_in[2];
    const float* a1d   = (const float*)d_in[3];
    const float* b1    = (const float*)d_in[4];
    const float* W2    = (const float*)d_in[5];
    const float* a2s   = (const float*)d_in[6];
    const float* a2d   = (const float*)d_in[7];
    const float* b2    = (const float*)d_in[8];
    const float* Wl    = (const float*)d_in[9];
    const float* bl    = (const float*)d_in[10];
    const int*   ei    = (const int*)d_in[11];
    const int*   batch = (const int*)d_in[12];

    int n = in_sizes[0] / INCH;
    int E = in_sizes[11] / 2;
    const int* srcA = ei;
    const int* dstA = ei + E;

    int total4 = n * FDIM / 4;
    int gemm_blocks = (n + 127) / 128;
    int agg_blocks = (n * 32 + 255) / 256;

    init_all<<<(total4 + 255) / 256, 256>>>(x, W1, W2, total4);
    scatter_edges<<<(E + 255) / 256, 256>>>(srcA, dstA, E);

    gemm_mma<<<gemm_blocks, 256>>>(a1s, a1d, n, 0);
    aggregate<<<agg_blocks, 256>>>(b1, n, 1);

    gemm_mma<<<gemm_blocks, 256>>>(a2s, a2d, n, 1);
    aggregate<<<agg_blocks, 256>>>(b2, n, 0);

    pool_kernel<<<(n + POOL_CHUNK - 1) / POOL_CHUNK, 128>>>(batch, n);
    head_kernel<<<GG, 128>>>(Wl, bl, (float*)d_out);
}

// round 16
// speedup vs baseline: 1.4533x; 1.0278x over previous
#include <cuda_runtime.h>
#include <cuda_fp16.h>
#include <stdint.h>
#include <math.h>

#define NN    50000
#define EMAX  800000
#define INCH  128
#define FDIM  128
#define HEADS 4
#define HID   32
#define OUTC  10
#define GG    64
#define NEG_SLOPE 0.2f
#define CAP   96

// ---------------- device scratch (zero-initialized at module load) ------
__device__ __align__(16) __half g_Ah[(size_t)NN * FDIM];
__device__ __align__(16) __half g_Hh[(size_t)NN * FDIM];
__device__ __align__(16) __half g_Wh1[FDIM * FDIM];
__device__ __align__(16) __half g_Wh2[FDIM * FDIM];
__device__ __align__(16) float g_ALS[(size_t)NN * HEADS];
__device__ __align__(16) float g_ALD[(size_t)NN * HEADS];
__device__ int   g_cursor[NN];          // ==0 at start of every call (restored by pool)
__device__ int   g_csrc[(size_t)NN * CAP];
__device__ float g_POOL[GG * FDIM];
__device__ float g_CNT[GG];

// ---------------- helpers ----------------
__device__ __forceinline__ float lrelu(float x) {
    return x > 0.f ? x : NEG_SLOPE * x;
}
__device__ __forceinline__ void ldm_x4(unsigned& r0, unsigned& r1, unsigned& r2,
                                       unsigned& r3, unsigned addr) {
    asm volatile("ldmatrix.sync.aligned.m8n8.x4.shared.b16 {%0,%1,%2,%3}, [%4];"
                 : "=r"(r0), "=r"(r1), "=r"(r2), "=r"(r3) : "r"(addr));
}
__device__ __forceinline__ void mma16816(float* d, const unsigned* a,
                                         unsigned b0, unsigned b1) {
    asm volatile(
        "mma.sync.aligned.m16n8k16.row.col.f32.f16.f16.f32 "
        "{%0,%1,%2,%3},{%4,%5,%6,%7},{%8,%9},{%0,%1,%2,%3};"
        : "+f"(d[0]), "+f"(d[1]), "+f"(d[2]), "+f"(d[3])
        : "r"(a[0]), "r"(a[1]), "r"(a[2]), "r"(a[3]), "r"(b0), "r"(b1));
}

// ---------------- launch 1: converts + zero + fused edge scatter ---------
__global__ void init_all(const float* __restrict__ x, const float* __restrict__ W1,
                         const float* __restrict__ W2,
                         const int* __restrict__ srcA, const int* __restrict__ dstA,
                         int total4, int E) {
    int i = blockIdx.x * blockDim.x + threadIdx.x;
    if (i < total4) {
        float4 v = __ldg((const float4*)x + i);
        uint2 w;
        *(half2*)&w.x = __floats2half2_rn(v.x, v.y);
        *(half2*)&w.y = __floats2half2_rn(v.z, v.w);
        ((uint2*)g_Ah)[i] = w;
    }
    if (i < FDIM * FDIM) {
        int k = i >> 7;
        int nn = i & 127;
        g_Wh1[nn * 128 + k] = __float2half(__ldg(&W1[i]));
        g_Wh2[nn * 128 + k] = __float2half(__ldg(&W2[i]));
    }
    if (i < GG * FDIM) g_POOL[i] = 0.f;
    if (i < GG) g_CNT[i] = 0.f;
    if (i < E) {
        int d = __ldg(&dstA[i]);
        int pos = atomicAdd(&g_cursor[d], 1);
        if (pos < CAP) g_csrc[(size_t)d * CAP + pos] = __ldg(&srcA[i]);
    }
}

// ---------------- launch 2/4 (4 = PROFILED): fp16 mma GEMM + dots --------
__global__ void __launch_bounds__(256) gemm_mma(const float* __restrict__ a_src,
                                                const float* __restrict__ a_dst,
                                                int n, int which) {
    __shared__ __half As[128 * 64];
    __shared__ __half Bs[128 * 64];
    const __half* Wh = which ? g_Wh2 : g_Wh1;
    const int tid = threadIdx.x;
    const int l = tid & 31;
    const int wid = tid >> 5;
    const int warp_m = wid >> 1;
    const int warp_n = wid & 1;
    const int row0 = blockIdx.x * 128;

    float acc[2][8][4];
#pragma unroll
    for (int i = 0; i < 2; i++)
#pragma unroll
        for (int j = 0; j < 8; j++)
#pragma unroll
            for (int c = 0; c < 4; c++) acc[i][j][c] = 0.f;

    const int grp = l >> 3;
    const int m8 = l & 7;
    int rowA[2];
#pragma unroll
    for (int i = 0; i < 2; i++) rowA[i] = warp_m * 32 + i * 16 + m8 + (grp & 1) * 8;
    const int kgA = grp >> 1;
    int nB[4];
#pragma unroll
    for (int jt = 0; jt < 4; jt++) nB[jt] = warp_n * 64 + jt * 16 + m8 + (grp >> 1) * 8;
    const int kgB = grp & 1;

    const unsigned as_base = (unsigned)__cvta_generic_to_shared(As);
    const unsigned bs_base = (unsigned)__cvta_generic_to_shared(Bs);

    for (int kc = 0; kc < 2; kc++) {
        if (kc) __syncthreads();
#pragma unroll
        for (int t = 0; t < 4; t++) {
            int e = tid + t * 256;
            int r = e >> 3;
            int g = e & 7;
            uint4 v = make_uint4(0, 0, 0, 0);
            if (row0 + r < n) v = ((const uint4*)g_Ah)[(size_t)(row0 + r) * 16 + kc * 8 + g];
            *((uint4*)(As + (r * 8 + (g ^ (r & 7))) * 8)) = v;
        }
#pragma unroll
        for (int t = 0; t < 4; t++) {
            int e = tid + t * 256;
            int r = e >> 3;
            int g = e & 7;
            uint4 v = ((const uint4*)Wh)[r * 16 + kc * 8 + g];
            *((uint4*)(Bs + (r * 8 + (g ^ (r & 7))) * 8)) = v;
        }
        __syncthreads();
#pragma unroll
        for (int ks = 0; ks < 4; ks++) {
            unsigned a[2][4];
            unsigned b[4][4];
#pragma unroll
            for (int i = 0; i < 2; i++) {
                int gr = ks * 2 + kgA;
                unsigned off = (unsigned)(rowA[i] * 8 + (gr ^ (rowA[i] & 7))) * 16u;
                ldm_x4(a[i][0], a[i][1], a[i][2], a[i][3], as_base + off);
            }
#pragma unroll
            for (int jt = 0; jt < 4; jt++) {
                int gr = ks * 2 + kgB;
                unsigned off = (unsigned)(nB[jt] * 8 + (gr ^ (nB[jt] & 7))) * 16u;
                ldm_x4(b[jt][0], b[jt][1], b[jt][2], b[jt][3], bs_base + off);
            }
#pragma unroll
            for (int i = 0; i < 2; i++)
#pragma unroll
                for (int j = 0; j < 8; j++) {
                    int jt = j >> 1;
                    int sel = (j & 1) * 2;
                    mma16816(acc[i][j], a[i], b[jt][sel], b[jt][sel + 1]);
                }
        }
    }

    const int quad = l >> 2;
    const int qt = l & 3;
    float wsrc[8][2];
    float wdst[8][2];
#pragma unroll
    for (int j = 0; j < 8; j++) {
        int c = warp_n * 64 + j * 8 + 2 * qt;
        wsrc[j][0] = __ldg(&a_src[c]);
        wsrc[j][1] = __ldg(&a_src[c + 1]);
        wdst[j][0] = __ldg(&a_dst[c]);
        wdst[j][1] = __ldg(&a_dst[c + 1]);
    }
    half2* H2 = (half2*)g_Hh;
#pragma unroll
    for (int i = 0; i < 2; i++) {
        int r_lo = row0 + warp_m * 32 + i * 16 + quad;
        int r_hi = r_lo + 8;
        float ps_lo[2] = {0.f, 0.f};
        float pd_lo[2] = {0.f, 0.f};
        float ps_hi[2] = {0.f, 0.f};
        float pd_hi[2] = {0.f, 0.f};
#pragma unroll
        for (int j = 0; j < 8; j++) {
            int hl = j >> 2;
            ps_lo[hl] += acc[i][j][0] * wsrc[j][0] + acc[i][j][1] * wsrc[j][1];
            pd_lo[hl] += acc[i][j][0] * wdst[j][0] + acc[i][j][1] * wdst[j][1];
            ps_hi[hl] += acc[i][j][2] * wsrc[j][0] + acc[i][j][3] * wsrc[j][1];
            pd_hi[hl] += acc[i][j][2] * wdst[j][0] + acc[i][j][3] * wdst[j][1];
        }
#pragma unroll
        for (int hl = 0; hl < 2; hl++) {
            ps_lo[hl] += __shfl_xor_sync(0xffffffffu, ps_lo[hl], 1);
            ps_lo[hl] += __shfl_xor_sync(0xffffffffu, ps_lo[hl], 2);
            pd_lo[hl] += __shfl_xor_sync(0xffffffffu, pd_lo[hl], 1);
            pd_lo[hl] += __shfl_xor_sync(0xffffffffu, pd_lo[hl], 2);
            ps_hi[hl] += __shfl_xor_sync(0xffffffffu, ps_hi[hl], 1);
            ps_hi[hl] += __shfl_xor_sync(0xffffffffu, ps_hi[hl], 2);
            pd_hi[hl] += __shfl_xor_sync(0xffffffffu, pd_hi[hl], 1);
            pd_hi[hl] += __shfl_xor_sync(0xffffffffu, pd_hi[hl], 2);
        }
        if (r_lo < n) {
#pragma unroll
            for (int j = 0; j < 8; j++) {
                int c = warp_n * 64 + j * 8 + 2 * qt;
                H2[(size_t)r_lo * 64 + (c >> 1)] =
                    __floats2half2_rn(acc[i][j][0], acc[i][j][1]);
            }
            if (qt == 0) {
#pragma unroll
                for (int hl = 0; hl < 2; hl++) {
                    g_ALS[r_lo * HEADS + warp_n * 2 + hl] = ps_lo[hl];
                    g_ALD[r_lo * HEADS + warp_n * 2 + hl] = pd_lo[hl];
                }
            }
        }
        if (r_hi < n) {
#pragma unroll
            for (int j = 0; j < 8; j++) {
                int c = warp_n * 64 + j * 8 + 2 * qt;
                H2[(size_t)r_hi * 64 + (c >> 1)] =
                    __floats2half2_rn(acc[i][j][2], acc[i][j][3]);
            }
            if (qt == 0) {
#pragma unroll
                for (int hl = 0; hl < 2; hl++) {
                    g_ALS[r_hi * HEADS + warp_n * 2 + hl] = ps_hi[hl];
                    g_ALD[r_hi * HEADS + warp_n * 2 + hl] = pd_hi[hl];
                }
            }
        }
    }
}

// ---------------- launch 3/5: bucket-gather aggregation ------------------
// ONE warp per node; parallel p via STS/LDS broadcast; HFMA2 fp16
// accumulate flushed to fp32 per 32-edge chunk.
__global__ void __launch_bounds__(256, 5) aggregate(const float* __restrict__ b,
                                                    int n, int do_elu) {
    __shared__ float s_p[8][32];
    const int wid = threadIdx.x >> 5;
    const int lane = threadIdx.x & 31;
    const int d = (blockIdx.x * 256 + threadIdx.x) >> 5;
    if (d >= n) return;
    const int h = lane >> 3;
    const int hp = lane & 3;
    const unsigned FULL = 0xffffffffu;
    const uint2* H2 = (const uint2*)g_Hh;
    float* sp = s_p[wid];

    const float ald_h = __ldg(&g_ALD[d * 4 + h]);
    const float ald_p = __ldg(&g_ALD[d * 4 + hp]);
    const int base = d * CAP;
    const int cnt_all = min(__ldg(&g_cursor[d]), CAP);

    // self loop (fp32)
    float p0 = __expf(lrelu(__ldg(&g_ALS[d * 4 + h]) + ald_h));
    uint2 u0 = __ldg(H2 + (size_t)d * 32 + lane);
    float2 f01 = __half22float2(*(const half2*)&u0.x);
    float2 f23 = __half22float2(*(const half2*)&u0.y);
    float4 acc = make_float4(p0 * f01.x, p0 * f01.y, p0 * f23.x, p0 * f23.y);
    float z = p0;

    const half2 hzero = __floats2half2_rn(0.f, 0.f);
    for (int j0 = 0; j0 < cnt_all; j0 += 32) {
        int cnt = min(32, cnt_all - j0);
        int my = (lane < cnt) ? __ldg(&g_csrc[base + j0 + lane]) : 0;
        half2 a01 = hzero;
        half2 a23 = hzero;
        int j = 0;
        for (; j + 8 <= cnt; j += 8) {
            int sq = __shfl_sync(FULL, my, j + (lane >> 2));
            float pq = __expf(lrelu(__ldg(&g_ALS[sq * 4 + hp]) + ald_p));
            sp[lane] = pq;
            int ss[8];
#pragma unroll
            for (int q = 0; q < 8; q++) ss[q] = __shfl_sync(FULL, my, j + q);
            uint2 uv[8];
#pragma unroll
            for (int q = 0; q < 8; q++) uv[q] = __ldg(H2 + (size_t)ss[q] * 32 + lane);
#pragma unroll
            for (int q = 0; q < 8; q++) {
                float p = sp[q * 4 + h];
                half2 ph = __float2half2_rn(p);
                a01 = __hfma2(ph, *(const half2*)&uv[q].x, a01);
                a23 = __hfma2(ph, *(const half2*)&uv[q].y, a23);
                z += p;
            }
        }
        for (; j + 4 <= cnt; j += 4) {
            int sq = __shfl_sync(FULL, my, j + ((lane >> 2) & 3));
            float pq = __expf(lrelu(__ldg(&g_ALS[sq * 4 + hp]) + ald_p));
            sp[lane] = pq;
            int ss[4];
#pragma unroll
            for (int q = 0; q < 4; q++) ss[q] = __shfl_sync(FULL, my, j + q);
            uint2 uv[4];
#pragma unroll
            for (int q = 0; q < 4; q++) uv[q] = __ldg(H2 + (size_t)ss[q] * 32 + lane);
#pragma unroll
            for (int q = 0; q < 4; q++) {
                float p = sp[q * 4 + h];
                half2 ph = __float2half2_rn(p);
                a01 = __hfma2(ph, *(const half2*)&uv[q].x, a01);
                a23 = __hfma2(ph, *(const half2*)&uv[q].y, a23);
                z += p;
            }
        }
        for (; j < cnt; j++) {
            int s = __shfl_sync(FULL, my, j);
            float p = __expf(lrelu(__ldg(&g_ALS[s * 4 + h]) + ald_h));
            uint2 us = __ldg(H2 + (size_t)s * 32 + lane);
            half2 ph = __float2half2_rn(p);
            a01 = __hfma2(ph, *(const half2*)&us.x, a01);
            a23 = __hfma2(ph, *(const half2*)&us.y, a23);
            z += p;
        }
        // flush fp16 partials
        float2 g01 = __half22float2(a01);
        float2 g23 = __half22float2(a23);
        acc.x += g01.x;
        acc.y += g01.y;
        acc.z += g23.x;
        acc.w += g23.y;
    }

    float inv = 1.f / z;
    float4 bb = __ldg((const float4*)b + lane);
    float4 o;
    o.x = acc.x * inv + bb.x;
    o.y = acc.y * inv + bb.y;
    o.z = acc.z * inv + bb.z;
    o.w = acc.w * inv + bb.w;
    if (do_elu) {
        o.x = o.x > 0.f ? o.x : expm1f(o.x);
        o.y = o.y > 0.f ? o.y : expm1f(o.y);
        o.z = o.z > 0.f ? o.z : expm1f(o.z);
        o.w = o.w > 0.f ? o.w : expm1f(o.w);
    }
    uint2 wout;
    *(half2*)&wout.x = __floats2half2_rn(o.x, o.y);
    *(half2*)&wout.y = __floats2half2_rn(o.z, o.w);
    ((uint2*)g_Ah)[(size_t)d * 32 + lane] = wout;
}

// ---------------- launch 6: pooling + cursor restore ---------------------
#define POOL_CHUNK 128
__global__ void __launch_bounds__(128) pool_kernel(const int* __restrict__ batch, int n) {
    int gid = blockIdx.x * POOL_CHUNK + threadIdx.x;
    if (gid < NN) g_cursor[gid] = 0;

    int t = threadIdx.x;
    int start = blockIdx.x * POOL_CHUNK;
    if (start >= n) return;
    int end = min(start + POOL_CHUNK, n);
    int curg = __ldg(&batch[start]);
    float acc = 0.f;
    float cnt = 0.f;
    for (int nn = start; nn < end; nn++) {
        int g = __ldg(&batch[nn]);
        if (g != curg) {
            atomicAdd(&g_POOL[curg * FDIM + t], acc);
            if (t == 0) atomicAdd(&g_CNT[curg], cnt);
            acc = 0.f;
            cnt = 0.f;
            curg = g;
        }
        acc += __half2float(g_Ah[(size_t)nn * FDIM + t]);
        cnt += 1.f;
    }
    atomicAdd(&g_POOL[curg * FDIM + t], acc);
    if (t == 0) atomicAdd(&g_CNT[curg], cnt);
}

// ---------------- launch 7: final linear + softmax -----------------------
__global__ void __launch_bounds__(128) head_kernel(const float* __restrict__ Wl,
                                                   const float* __restrict__ bl,
                                                   float* __restrict__ out) {
    int g = blockIdx.x;
    __shared__ float p[FDIM];
    __shared__ float lg[OUTC];
    float c = fmaxf(g_CNT[g], 1.f);
    p[threadIdx.x] = g_POOL[g * FDIM + threadIdx.x] / c;
    __syncthreads();
    if (threadIdx.x < OUTC) {
        float s = bl[threadIdx.x];
#pragma unroll 16
        for (int k = 0; k < FDIM; k++) s += p[k] * Wl[k * OUTC + threadIdx.x];
        lg[threadIdx.x] = s;
    }
    __syncthreads();
    if (threadIdx.x == 0) {
        float mx = -1e30f;
        for (int o = 0; o < OUTC; o++) mx = fmaxf(mx, lg[o]);
        float ssum = 0.f;
        float e[OUTC];
        for (int o = 0; o < OUTC; o++) {
            e[o] = __expf(lg[o] - mx);
            ssum += e[o];
        }
        for (int o = 0; o < OUTC; o++) out[g * OUTC + o] = e[o] / ssum;
    }
}

// ---------------- host orchestration ----------------
extern "C" void kernel_launch(void* const* d_in, const int* in_sizes, int n_in,
                              void* d_out, int out_size) {
    const float* x     = (const float*)d_in[0];
    const float* W1    = (const float*)d_in[1];
    const float* a1s   = (const float*)d_in[2];
    const float* a1d   = (const float*)d_in[3];
    const float* b1    = (const float*)d_in[4];
    const float* W2    = (const float*)d_in[5];
    const float* a2s   = (const float*)d_in[6];
    const float* a2d   = (const float*)d_in[7];
    const float* b2    = (const float*)d_in[8];
    const float* Wl    = (const float*)d_in[9];
    const float* bl    = (const float*)d_in[10];
    const int*   ei    = (const int*)d_in[11];
    const int*   batch = (const int*)d_in[12];

    int n = in_sizes[0] / INCH;
    int E = in_sizes[11] / 2;
    const int* srcA = ei;
    const int* dstA = ei + E;

    int total4 = n * FDIM / 4;
    int gemm_blocks = (n + 127) / 128;
    int agg_blocks = (n * 32 + 255) / 256;

    // 1: init (converts + zero + edge scatter)
    init_all<<<(total4 + 255) / 256, 256>>>(x, W1, W2, srcA, dstA, total4, E);

    // 2: gemm1  3: agg1  4 (profiled): gemm2  5: agg2
    gemm_mma<<<gemm_blocks, 256>>>(a1s, a1d, n, 0);
    aggregate<<<agg_blocks, 256>>>(b1, n, 1);

    gemm_mma<<<gemm_blocks, 256>>>(a2s, a2d, n, 1);
    aggregate<<<agg_blocks, 256>>>(b2, n, 0);

    // 6: pool (+cursor restore)  7: head
    pool_kernel<<<(n + POOL_CHUNK - 1) / POOL_CHUNK, 128>>>(batch, n);
    head_kernel<<<GG, 128>>>(Wl, bl, (float*)d_out);
}

// round 17
// speedup vs baseline: 1.4693x; 1.0110x over previous
#include <cuda_runtime.h>
#include <cuda_fp16.h>
#include <stdint.h>
#include <math.h>

#define NN    50000
#define EMAX  800000
#define INCH  128
#define FDIM  128
#define HEADS 4
#define HID   32
#define OUTC  10
#define GG    64
#define NEG_SLOPE 0.2f
#define CAP   96

// ---------------- device scratch (zero-initialized at module load) ------
__device__ __align__(16) __half g_Ah[(size_t)NN * FDIM];
__device__ __align__(16) __half g_Hh[(size_t)NN * FDIM];
__device__ __align__(16) __half g_Wh1[FDIM * FDIM];
__device__ __align__(16) __half g_Wh2[FDIM * FDIM];
__device__ __align__(16) float g_ALS[(size_t)NN * HEADS];
__device__ __align__(16) float g_ALD[(size_t)NN * HEADS];
__device__ int   g_cursor[NN];          // ==0 at start of every call (restored by pool)
__device__ int   g_csrc[(size_t)NN * CAP];
__device__ float g_POOL[GG * FDIM];
__device__ float g_CNT[GG];

// ---------------- helpers ----------------
__device__ __forceinline__ float lrelu(float x) {
    return x > 0.f ? x : NEG_SLOPE * x;
}
__device__ __forceinline__ void ldm_x4(unsigned& r0, unsigned& r1, unsigned& r2,
                                       unsigned& r3, unsigned addr) {
    asm volatile("ldmatrix.sync.aligned.m8n8.x4.shared.b16 {%0,%1,%2,%3}, [%4];"
                 : "=r"(r0), "=r"(r1), "=r"(r2), "=r"(r3) : "r"(addr));
}
__device__ __forceinline__ void mma16816(float* d, const unsigned* a,
                                         unsigned b0, unsigned b1) {
    asm volatile(
        "mma.sync.aligned.m16n8k16.row.col.f32.f16.f16.f32 "
        "{%0,%1,%2,%3},{%4,%5,%6,%7},{%8,%9},{%0,%1,%2,%3};"
        : "+f"(d[0]), "+f"(d[1]), "+f"(d[2]), "+f"(d[3])
        : "r"(a[0]), "r"(a[1]), "r"(a[2]), "r"(a[3]), "r"(b0), "r"(b1));
}
__device__ __forceinline__ void cp_async16(unsigned dst, const void* src, bool pred) {
    int sz = pred ? 16 : 0;
    asm volatile("cp.async.cg.shared.global [%0], [%1], 16, %2;"
                 :: "r"(dst), "l"(src), "r"(sz));
}
__device__ __forceinline__ void cp_commit() {
    asm volatile("cp.async.commit_group;");
}
__device__ __forceinline__ void cp_wait1() {
    asm volatile("cp.async.wait_group 1;");
}
__device__ __forceinline__ void cp_wait0() {
    asm volatile("cp.async.wait_group 0;");
}

// ---------------- launch 1: converts + zero + fused edge scatter ---------
__global__ void init_all(const float* __restrict__ x, const float* __restrict__ W1,
                         const float* __restrict__ W2,
                         const int* __restrict__ srcA, const int* __restrict__ dstA,
                         int total4, int E) {
    int i = blockIdx.x * blockDim.x + threadIdx.x;
    if (i < total4) {
        float4 v = __ldg((const float4*)x + i);
        uint2 w;
        *(half2*)&w.x = __floats2half2_rn(v.x, v.y);
        *(half2*)&w.y = __floats2half2_rn(v.z, v.w);
        ((uint2*)g_Ah)[i] = w;
    }
    if (i < FDIM * FDIM) {
        int k = i >> 7;
        int nn = i & 127;
        g_Wh1[nn * 128 + k] = __float2half(__ldg(&W1[i]));
        g_Wh2[nn * 128 + k] = __float2half(__ldg(&W2[i]));
    }
    if (i < GG * FDIM) g_POOL[i] = 0.f;
    if (i < GG) g_CNT[i] = 0.f;
    if (i < E) {
        int d = __ldg(&dstA[i]);
        int pos = atomicAdd(&g_cursor[d], 1);
        if (pos < CAP) g_csrc[(size_t)d * CAP + pos] = __ldg(&srcA[i]);
    }
}

// ---------------- launch 2/4 (4 = PROFILED): pipelined fp16 mma GEMM -----
// BK=32, 4 k-chunks, cp.async double-buffered. Swizzle: granule g^((r>>1)&3)
// within 64B rows (conflict-free for ldmatrix 8-row groups).
__global__ void __launch_bounds__(256) gemm_mma(const float* __restrict__ a_src,
                                                const float* __restrict__ a_dst,
                                                int n, int which) {
    __shared__ __half As[2][128 * 32];
    __shared__ __half Bs[2][128 * 32];
    const __half* Wh = which ? g_Wh2 : g_Wh1;
    const int tid = threadIdx.x;
    const int l = tid & 31;
    const int wid = tid >> 5;
    const int warp_m = wid >> 1;
    const int warp_n = wid & 1;
    const int row0 = blockIdx.x * 128;

    float acc[2][8][4];
#pragma unroll
    for (int i = 0; i < 2; i++)
#pragma unroll
        for (int j = 0; j < 8; j++)
#pragma unroll
            for (int c = 0; c < 4; c++) acc[i][j][c] = 0.f;

    const int grp = l >> 3;
    const int m8 = l & 7;
    int rowA[2];
#pragma unroll
    for (int i = 0; i < 2; i++) rowA[i] = warp_m * 32 + i * 16 + m8 + (grp & 1) * 8;
    const int kgA = grp >> 1;
    int nB[4];
#pragma unroll
    for (int jt = 0; jt < 4; jt++) nB[jt] = warp_n * 64 + jt * 16 + m8 + (grp >> 1) * 8;
    const int kgB = grp & 1;

    const unsigned as_base = (unsigned)__cvta_generic_to_shared(&As[0][0]);
    const unsigned bs_base = (unsigned)__cvta_generic_to_shared(&Bs[0][0]);

    // issue async load of k-chunk c into buffer buf
    auto load_chunk = [&](int buf, int c) {
#pragma unroll
        for (int t = 0; t < 2; t++) {
            int e = tid + t * 256;
            int r = e >> 2;            // 0..127
            int g = e & 3;             // granule within 64B row
            int sg = g ^ ((r >> 1) & 3);
            unsigned adst = as_base + (unsigned)buf * 8192u + (unsigned)(r * 4 + sg) * 16u;
            const void* asrc = g_Ah + (size_t)(row0 + r) * 128 + c * 32 + g * 8;
            cp_async16(adst, asrc, row0 + r < n);
            unsigned bdst = bs_base + (unsigned)buf * 8192u + (unsigned)(r * 4 + sg) * 16u;
            const void* bsrc = Wh + (size_t)r * 128 + c * 32 + g * 8;
            cp_async16(bdst, bsrc, true);
        }
        cp_commit();
    };

    load_chunk(0, 0);
    load_chunk(1, 1);

    for (int c = 0; c < 4; c++) {
        if (c < 3) cp_wait1(); else cp_wait0();
        __syncthreads();
        const int buf = c & 1;
        const unsigned abuf = as_base + (unsigned)buf * 8192u;
        const unsigned bbuf = bs_base + (unsigned)buf * 8192u;
#pragma unroll
        for (int ks = 0; ks < 2; ks++) {
            unsigned a[2][4];
            unsigned b[4][4];
#pragma unroll
            for (int i = 0; i < 2; i++) {
                int gr = ks * 2 + kgA;
                int row = rowA[i];
                unsigned off = (unsigned)(row * 4 + (gr ^ ((row >> 1) & 3))) * 16u;
                ldm_x4(a[i][0], a[i][1], a[i][2], a[i][3], abuf + off);
            }
#pragma unroll
            for (int jt = 0; jt < 4; jt++) {
                int gr = ks * 2 + kgB;
                int row = nB[jt];
                unsigned off = (unsigned)(row * 4 + (gr ^ ((row >> 1) & 3))) * 16u;
                ldm_x4(b[jt][0], b[jt][1], b[jt][2], b[jt][3], bbuf + off);
            }
#pragma unroll
            for (int i = 0; i < 2; i++)
#pragma unroll
                for (int j = 0; j < 8; j++) {
                    int jt = j >> 1;
                    int sel = (j & 1) * 2;
                    mma16816(acc[i][j], a[i], b[jt][sel], b[jt][sel + 1]);
                }
        }
        __syncthreads();
        if (c + 2 < 4) load_chunk(buf, c + 2);
    }

    // ---- epilogue: store H fp16 + fused attention logits ----
    const int quad = l >> 2;
    const int qt = l & 3;
    float wsrc[8][2];
    float wdst[8][2];
#pragma unroll
    for (int j = 0; j < 8; j++) {
        int c = warp_n * 64 + j * 8 + 2 * qt;
        wsrc[j][0] = __ldg(&a_src[c]);
        wsrc[j][1] = __ldg(&a_src[c + 1]);
        wdst[j][0] = __ldg(&a_dst[c]);
        wdst[j][1] = __ldg(&a_dst[c + 1]);
    }
    half2* H2 = (half2*)g_Hh;
#pragma unroll
    for (int i = 0; i < 2; i++) {
        int r_lo = row0 + warp_m * 32 + i * 16 + quad;
        int r_hi = r_lo + 8;
        float ps_lo[2] = {0.f, 0.f};
        float pd_lo[2] = {0.f, 0.f};
        float ps_hi[2] = {0.f, 0.f};
        float pd_hi[2] = {0.f, 0.f};
#pragma unroll
        for (int j = 0; j < 8; j++) {
            int hl = j >> 2;
            ps_lo[hl] += acc[i][j][0] * wsrc[j][0] + acc[i][j][1] * wsrc[j][1];
            pd_lo[hl] += acc[i][j][0] * wdst[j][0] + acc[i][j][1] * wdst[j][1];
            ps_hi[hl] += acc[i][j][2] * wsrc[j][0] + acc[i][j][3] * wsrc[j][1];
            pd_hi[hl] += acc[i][j][2] * wdst[j][0] + acc[i][j][3] * wdst[j][1];
        }
#pragma unroll
        for (int hl = 0; hl < 2; hl++) {
            ps_lo[hl] += __shfl_xor_sync(0xffffffffu, ps_lo[hl], 1);
            ps_lo[hl] += __shfl_xor_sync(0xffffffffu, ps_lo[hl], 2);
            pd_lo[hl] += __shfl_xor_sync(0xffffffffu, pd_lo[hl], 1);
            pd_lo[hl] += __shfl_xor_sync(0xffffffffu, pd_lo[hl], 2);
            ps_hi[hl] += __shfl_xor_sync(0xffffffffu, ps_hi[hl], 1);
            ps_hi[hl] += __shfl_xor_sync(0xffffffffu, ps_hi[hl], 2);
            pd_hi[hl] += __shfl_xor_sync(0xffffffffu, pd_hi[hl], 1);
            pd_hi[hl] += __shfl_xor_sync(0xffffffffu, pd_hi[hl], 2);
        }
        if (r_lo < n) {
#pragma unroll
            for (int j = 0; j < 8; j++) {
                int c = warp_n * 64 + j * 8 + 2 * qt;
                H2[(size_t)r_lo * 64 + (c >> 1)] =
                    __floats2half2_rn(acc[i][j][0], acc[i][j][1]);
            }
            if (qt == 0) {
#pragma unroll
                for (int hl = 0; hl < 2; hl++) {
                    g_ALS[r_lo * HEADS + warp_n * 2 + hl] = ps_lo[hl];
                    g_ALD[r_lo * HEADS + warp_n * 2 + hl] = pd_lo[hl];
                }
            }
        }
        if (r_hi < n) {
#pragma unroll
            for (int j = 0; j < 8; j++) {
                int c = warp_n * 64 + j * 8 + 2 * qt;
                H2[(size_t)r_hi * 64 + (c >> 1)] =
                    __floats2half2_rn(acc[i][j][2], acc[i][j][3]);
            }
            if (qt == 0) {
#pragma unroll
                for (int hl = 0; hl < 2; hl++) {
                    g_ALS[r_hi * HEADS + warp_n * 2 + hl] = ps_hi[hl];
                    g_ALD[r_hi * HEADS + warp_n * 2 + hl] = pd_hi[hl];
                }
            }
        }
    }
}

// ---------------- launch 3/5: bucket-gather aggregation ------------------
__global__ void __launch_bounds__(256, 5) aggregate(const float* __restrict__ b,
                                                    int n, int do_elu) {
    __shared__ float s_p[8][32];
    const int wid = threadIdx.x >> 5;
    const int lane = threadIdx.x & 31;
    const int d = (blockIdx.x * 256 + threadIdx.x) >> 5;
    if (d >= n) return;
    const int h = lane >> 3;
    const int hp = lane & 3;
    const unsigned FULL = 0xffffffffu;
    const uint2* H2 = (const uint2*)g_Hh;
    float* sp = s_p[wid];

    const float ald_h = __ldg(&g_ALD[d * 4 + h]);
    const float ald_p = __ldg(&g_ALD[d * 4 + hp]);
    const int base = d * CAP;
    const int cnt_all = min(__ldg(&g_cursor[d]), CAP);

    float p0 = __expf(lrelu(__ldg(&g_ALS[d * 4 + h]) + ald_h));
    uint2 u0 = __ldg(H2 + (size_t)d * 32 + lane);
    float2 f01 = __half22float2(*(const half2*)&u0.x);
    float2 f23 = __half22float2(*(const half2*)&u0.y);
    float4 acc = make_float4(p0 * f01.x, p0 * f01.y, p0 * f23.x, p0 * f23.y);
    float z = p0;

    const half2 hzero = __floats2half2_rn(0.f, 0.f);
    for (int j0 = 0; j0 < cnt_all; j0 += 32) {
        int cnt = min(32, cnt_all - j0);
        int my = (lane < cnt) ? __ldg(&g_csrc[base + j0 + lane]) : 0;
        half2 a01 = hzero;
        half2 a23 = hzero;
        int j = 0;
        for (; j + 8 <= cnt; j += 8) {
            int sq = __shfl_sync(FULL, my, j + (lane >> 2));
            float pq = __expf(lrelu(__ldg(&g_ALS[sq * 4 + hp]) + ald_p));
            sp[lane] = pq;
            int ss[8];
#pragma unroll
            for (int q = 0; q < 8; q++) ss[q] = __shfl_sync(FULL, my, j + q);
            uint2 uv[8];
#pragma unroll
            for (int q = 0; q < 8; q++) uv[q] = __ldg(H2 + (size_t)ss[q] * 32 + lane);
#pragma unroll
            for (int q = 0; q < 8; q++) {
                float p = sp[q * 4 + h];
                half2 ph = __float2half2_rn(p);
                a01 = __hfma2(ph, *(const half2*)&uv[q].x, a01);
                a23 = __hfma2(ph, *(const half2*)&uv[q].y, a23);
                z += p;
            }
        }
        for (; j + 4 <= cnt; j += 4) {
            int sq = __shfl_sync(FULL, my, j + ((lane >> 2) & 3));
            float pq = __expf(lrelu(__ldg(&g_ALS[sq * 4 + hp]) + ald_p));
            sp[lane] = pq;
            int ss[4];
#pragma unroll
            for (int q = 0; q < 4; q++) ss[q] = __shfl_sync(FULL, my, j + q);
            uint2 uv[4];
#pragma unroll
            for (int q = 0; q < 4; q++) uv[q] = __ldg(H2 + (size_t)ss[q] * 32 + lane);
#pragma unroll
            for (int q = 0; q < 4; q++) {
                float p = sp[q * 4 + h];
                half2 ph = __float2half2_rn(p);
                a01 = __hfma2(ph, *(const half2*)&uv[q].x, a01);
                a23 = __hfma2(ph, *(const half2*)&uv[q].y, a23);
                z += p;
            }
        }
        for (; j < cnt; j++) {
            int s = __shfl_sync(FULL, my, j);
            float p = __expf(lrelu(__ldg(&g_ALS[s * 4 + h]) + ald_h));
            uint2 us = __ldg(H2 + (size_t)s * 32 + lane);
            half2 ph = __float2half2_rn(p);
            a01 = __hfma2(ph, *(const half2*)&us.x, a01);
            a23 = __hfma2(ph, *(const half2*)&us.y, a23);
            z += p;
        }
        float2 g01 = __half22float2(a01);
        float2 g23 = __half22float2(a23);
        acc.x += g01.x;
        acc.y += g01.y;
        acc.z += g23.x;
        acc.w += g23.y;
    }

    float inv = 1.f / z;
    float4 bb = __ldg((const float4*)b + lane);
    float4 o;
    o.x = acc.x * inv + bb.x;
    o.y = acc.y * inv + bb.y;
    o.z = acc.z * inv + bb.z;
    o.w = acc.w * inv + bb.w;
    if (do_elu) {
        o.x = o.x > 0.f ? o.x : expm1f(o.x);
        o.y = o.y > 0.f ? o.y : expm1f(o.y);
        o.z = o.z > 0.f ? o.z : expm1f(o.z);
        o.w = o.w > 0.f ? o.w : expm1f(o.w);
    }
    uint2 wout;
    *(half2*)&wout.x = __floats2half2_rn(o.x, o.y);
    *(half2*)&wout.y = __floats2half2_rn(o.z, o.w);
    ((uint2*)g_Ah)[(size_t)d * 32 + lane] = wout;
}

// ---------------- launch 6: pooling + cursor restore ---------------------
#define POOL_CHUNK 128
__global__ void __launch_bounds__(128) pool_kernel(const int* __restrict__ batch, int n) {
    int gid = blockIdx.x * POOL_CHUNK + threadIdx.x;
    if (gid < NN) g_cursor[gid] = 0;

    int t = threadIdx.x;
    int start = blockIdx.x * POOL_CHUNK;
    if (start >= n) return;
    int end = min(start + POOL_CHUNK, n);
    int curg = __ldg(&batch[start]);
    float acc = 0.f;
    float cnt = 0.f;
    for (int nn = start; nn < end; nn++) {
        int g = __ldg(&batch[nn]);
        if (g != curg) {
            atomicAdd(&g_POOL[curg * FDIM + t], acc);
            if (t == 0) atomicAdd(&g_CNT[curg], cnt);
            acc = 0.f;
            cnt = 0.f;
            curg = g;
        }
        acc += __half2float(g_Ah[(size_t)nn * FDIM + t]);
        cnt += 1.f;
    }
    atomicAdd(&g_POOL[curg * FDIM + t], acc);
    if (t == 0) atomicAdd(&g_CNT[curg], cnt);
}

// ---------------- launch 7: final linear + softmax -----------------------
__global__ void __launch_bounds__(128) head_kernel(const float* __restrict__ Wl,
                                                   const float* __restrict__ bl,
                                                   float* __restrict__ out) {
    int g = blockIdx.x;
    __shared__ float p[FDIM];
    __shared__ float lg[OUTC];
    float c = fmaxf(g_CNT[g], 1.f);
    p[threadIdx.x] = g_POOL[g * FDIM + threadIdx.x] / c;
    __syncthreads();
    if (threadIdx.x < OUTC) {
        float s = bl[threadIdx.x];
#pragma unroll 16
        for (int k = 0; k < FDIM; k++) s += p[k] * Wl[k * OUTC + threadIdx.x];
        lg[threadIdx.x] = s;
    }
    __syncthreads();
    if (threadIdx.x == 0) {
        float mx = -1e30f;
        for (int o = 0; o < OUTC; o++) mx = fmaxf(mx, lg[o]);
        float ssum = 0.f;
        float e[OUTC];
        for (int o = 0; o < OUTC; o++) {
            e[o] = __expf(lg[o] - mx);
            ssum += e[o];
        }
        for (int o = 0; o < OUTC; o++) out[g * OUTC + o] = e[o] / ssum;
    }
}

// ---------------- host orchestration ----------------
extern "C" void kernel_launch(void* const* d_in, const int* in_sizes, int n_in,
                              void* d_out, int out_size) {
    const float* x     = (const float*)d_in[0];
    const float* W1    = (const float*)d_in[1];
    const float* a1s   = (const float*)d_in[2];
    const float* a1d   = (const float*)d_in[3];
    const float* b1    = (const float*)d_in[4];
    const float* W2    = (const float*)d_in[5];
    const float* a2s   = (const float*)d_in[6];
    const float* a2d   = (const float*)d_in[7];
    const float* b2    = (const float*)d_in[8];
    const float* Wl    = (const float*)d_in[9];
    const float* bl    = (const float*)d_in[10];
    const int*   ei    = (const int*)d_in[11];
    const int*   batch = (const int*)d_in[12];

    int n = in_sizes[0] / INCH;
    int E = in_sizes[11] / 2;
    const int* srcA = ei;
    const int* dstA = ei + E;

    int total4 = n * FDIM / 4;
    int gemm_blocks = (n + 127) / 128;
    int agg_blocks = (n * 32 + 255) / 256;

    // 1: init (converts + zero + edge scatter)
    init_all<<<(total4 + 255) / 256, 256>>>(x, W1, W2, srcA, dstA, total4, E);

    // 2: gemm1  3: agg1  4 (profiled): gemm2  5: agg2
    gemm_mma<<<gemm_blocks, 256>>>(a1s, a1d, n, 0);
    aggregate<<<agg_blocks, 256>>>(b1, n, 1);

    gemm_mma<<<gemm_blocks, 256>>>(a2s, a2d, n, 1);
    aggregate<<<agg_blocks, 256>>>(b2, n, 0);

    // 6: pool (+cursor restore)  7: head
    pool_kernel<<<(n + POOL_CHUNK - 1) / POOL_CHUNK, 128>>>(batch, n);
    head_kernel<<<GG, 128>>>(Wl, bl, (float*)d_out);
}